// round 10
// baseline (speedup 1.0000x reference)
#include <cuda_runtime.h>
#include <cuda_bf16.h>
#include <cstdint>
#include <math.h>

#define BATCH   2
#define SEQ     2048
#define NEMB    2048
#define NHEAD   16
#define HD      128
#define QKV_COLS 2304          // (16+2)*128
#define ROWS    (BATCH*SEQ)    // 4096

// ---------------- scratch (no cudaMalloc allowed) ----------------
__device__ float g_qkv[ROWS * QKV_COLS];
__device__ __nv_bfloat16 g_x_hi[ROWS * NEMB];
__device__ __nv_bfloat16 g_x_lo[ROWS * NEMB];
__device__ __nv_bfloat16 g_wat_hi[QKV_COLS * NEMB];   // transposed [N][K]
__device__ __nv_bfloat16 g_wat_lo[QKV_COLS * NEMB];
__device__ __nv_bfloat16 g_wot_hi[NEMB * NEMB];       // transposed [N][K]
__device__ __nv_bfloat16 g_wot_lo[NEMB * NEMB];
__device__ __nv_bfloat16 g_att_hi[ROWS * NEMB];
__device__ __nv_bfloat16 g_att_lo[ROWS * NEMB];
__device__ __nv_bfloat16 g_q_hi[ROWS * NEMB];         // post-RoPE q
__device__ __nv_bfloat16 g_q_lo[ROWS * NEMB];
__device__ __nv_bfloat16 g_k_hi[ROWS * HD];           // post-RoPE k [b*SEQ+t][128]
__device__ __nv_bfloat16 g_k_lo[ROWS * HD];
__device__ __nv_bfloat16 g_vt_hi[BATCH * HD * SEQ];   // v transposed [b][d][t]
__device__ __nv_bfloat16 g_vt_lo[BATCH * HD * SEQ];

// ---------------- PTX helpers (baseline ISA only: sm_80-class) ----------------
__device__ __forceinline__ uint32_t smem_u32(const void* p) {
    uint32_t a;
    asm("{ .reg .u64 t; cvta.to.shared.u64 t, %1; cvt.u32.u64 %0, t; }" : "=r"(a) : "l"(p));
    return a;
}
#define CP_ASYNC16(s, g) \
    asm volatile("cp.async.cg.shared.global [%0], [%1], 16;" :: "r"(s), "l"(g) : "memory")
#define CP_COMMIT() asm volatile("cp.async.commit_group;" ::: "memory")
#define CP_WAIT1()  asm volatile("cp.async.wait_group 1;" ::: "memory")
#define CP_WAIT0()  asm volatile("cp.async.wait_group 0;" ::: "memory")
#define LDSM_X4(r, a) \
    asm volatile("ldmatrix.sync.aligned.m8n8.x4.shared.b16 {%0,%1,%2,%3}, [%4];" \
        : "=r"((r)[0]), "=r"((r)[1]), "=r"((r)[2]), "=r"((r)[3]) : "r"(a))

__device__ __forceinline__ void mma_bf16(float* d, const uint32_t* a, uint32_t b0, uint32_t b1) {
    asm volatile(
        "mma.sync.aligned.m16n8k16.row.col.f32.bf16.bf16.f32 "
        "{%0,%1,%2,%3}, {%4,%5,%6,%7}, {%8,%9}, {%0,%1,%2,%3};"
        : "+f"(d[0]), "+f"(d[1]), "+f"(d[2]), "+f"(d[3])
        : "r"(a[0]), "r"(a[1]), "r"(a[2]), "r"(a[3]), "r"(b0), "r"(b1));
}
__device__ __forceinline__ uint32_t pack_bf16(float x, float y) {
    __nv_bfloat162 t = __floats2bfloat162_rn(x, y);
    return *(uint32_t*)&t;
}

// ---------------------------------------------------------------------------
// HMMA split-bf16 GEMM: C[M,N] fp32 = (Ah+Al)[M,K] @ (Bh+Bl)[N,K]^T
// 128x128 CTA tile, k-chunk 32, 3-stage cp.async, ONE syncthreads per chunk.
// ---------------------------------------------------------------------------
#define TROW_B   80
#define TBUF_B   (128 * TROW_B)
#define GSTAGE_B (4 * TBUF_B)          // 40960
#define GEMM_SMEM (3 * GSTAGE_B)       // 122880

__global__ __launch_bounds__(256, 1) void hmma_gemm_kernel(
    const __nv_bfloat16* __restrict__ Ah, const __nv_bfloat16* __restrict__ Al,
    const __nv_bfloat16* __restrict__ Bh, const __nv_bfloat16* __restrict__ Bl,
    float* __restrict__ C, int M, int N, int K)
{
    extern __shared__ char smem[];
    const uint32_t sb = smem_u32(smem);
    const int tid  = threadIdx.x;
    const int lane = tid & 31;
    const int warp = tid >> 5;
    const int m0 = blockIdx.y * 128, n0 = blockIdx.x * 128;
    const int wm = (warp >> 2) * 64, wn = (warp & 3) * 32;

    const int crow  = tid >> 1;
    const int cchk  = (tid & 1) * 2;
    const char* gsrc[4];
    gsrc[0] = (const char*)(Ah + (size_t)(m0 + crow) * K);
    gsrc[1] = (const char*)(Al + (size_t)(m0 + crow) * K);
    gsrc[2] = (const char*)(Bh + (size_t)(n0 + crow) * K);
    gsrc[3] = (const char*)(Bl + (size_t)(n0 + crow) * K);
    const uint32_t sdst = sb + crow * TROW_B + cchk * 16;

    const int nch = K / 32;
    float acc[4][4][4] = {};
    const int lr = lane & 15;
    const int lc = lane >> 4;

    auto issue = [&](int ch, int st) {
        const uint32_t so = st * GSTAGE_B;
        #pragma unroll
        for (int b = 0; b < 4; b++) {
            const char* g = gsrc[b] + (size_t)ch * 64 + cchk * 16;
            uint32_t s = sdst + so + b * TBUF_B;
            CP_ASYNC16(s, g);
            CP_ASYNC16(s + 16, g + 16);
        }
        CP_COMMIT();
    };

    issue(0, 0);
    issue(1, 1);
    int stg = 0;
    for (int ch = 0; ch < nch; ch++) {
        if (ch == nch - 1) { CP_WAIT0(); } else { CP_WAIT1(); }
        __syncthreads();
        if (ch + 2 < nch) issue(ch + 2, stg == 0 ? 2 : stg - 1);

        const uint32_t stage = sb + stg * GSTAGE_B;
        const uint32_t aoff  = stage + (wm + lr) * TROW_B + lc * 16;
        const uint32_t boff  = stage + 2 * TBUF_B + (wn + lr) * TROW_B + lc * 16;

        #pragma unroll
        for (int kh = 0; kh < 2; kh++) {
            const uint32_t ko = kh * 32;
            uint32_t ah[4][4], al[4][4], bh[2][4], bl[2][4];
            #pragma unroll
            for (int ma = 0; ma < 4; ma++) {
                uint32_t ad = aoff + ma * (16 * TROW_B) + ko;
                LDSM_X4(ah[ma], ad);
                LDSM_X4(al[ma], ad + TBUF_B);
            }
            #pragma unroll
            for (int ng = 0; ng < 2; ng++) {
                uint32_t bd = boff + ng * (16 * TROW_B) + ko;
                LDSM_X4(bh[ng], bd);
                LDSM_X4(bl[ng], bd + TBUF_B);
            }
            #pragma unroll
            for (int ma = 0; ma < 4; ma++)
                #pragma unroll
                for (int na = 0; na < 4; na++) {
                    const int ng = na >> 1, hi = na & 1;
                    mma_bf16(acc[ma][na], ah[ma], bh[ng][hi], bh[ng][hi + 2]);
                    mma_bf16(acc[ma][na], ah[ma], bl[ng][hi], bl[ng][hi + 2]);
                    mma_bf16(acc[ma][na], al[ma], bh[ng][hi], bh[ng][hi + 2]);
                }
        }
        stg = (stg == 2) ? 0 : stg + 1;
    }

    const int gr = lane >> 2, gc = (lane & 3) * 2;
    #pragma unroll
    for (int ma = 0; ma < 4; ma++) {
        #pragma unroll
        for (int na = 0; na < 4; na++) {
            size_t r = (size_t)(m0 + wm + ma * 16 + gr);
            size_t c = (size_t)(n0 + wn + na * 8 + gc);
            *(float2*)&C[r * N + c]       = make_float2(acc[ma][na][0], acc[ma][na][1]);
            *(float2*)&C[(r + 8) * N + c] = make_float2(acc[ma][na][2], acc[ma][na][3]);
        }
    }
}

// ---------------------------------------------------------------------------
// HMMA flash attention (no-max softmax), split-bf16, 3-stage K/V pipeline.
// Block = (128 q rows, head, batch), 8 warps x (16 rows x 32 keys).
// ---------------------------------------------------------------------------
#define QSTR 272
#define KSTR 272
#define VSTR 80
#define SM_QB  (128*QSTR)               // per-split Q bytes (34816)
#define SM_K   (2*SM_QB)                // 69632
#define KBUF   (32*KSTR)                // 8704
#define KSTAGE (2*KBUF)                 // 17408
#define SM_V   (SM_K + 3*KSTAGE)        // 121856
#define VBUF   (128*VSTR)               // 10240
#define VSTAGE (2*VBUF)                 // 20480
#define ATT_SMEM (SM_V + 3*VSTAGE)      // 183296

__global__ __launch_bounds__(256, 1) void hmma_attn_kernel(
    const __nv_bfloat16* __restrict__ qh_g, const __nv_bfloat16* __restrict__ ql_g,
    const __nv_bfloat16* __restrict__ kh_g, const __nv_bfloat16* __restrict__ kl_g,
    const __nv_bfloat16* __restrict__ vth_g, const __nv_bfloat16* __restrict__ vtl_g,
    __nv_bfloat16* __restrict__ oh_g, __nv_bfloat16* __restrict__ ol_g)
{
    extern __shared__ char smem[];
    const uint32_t sb = smem_u32(smem);
    const int qt = blockIdx.x, h = blockIdx.y, b = blockIdx.z;
    const int tid = threadIdx.x, lane = tid & 31, warp = tid >> 5;
    const int lr = lane & 15, lc = lane >> 4;
    const int gr = lane >> 2, gc = (lane & 3) * 2;

    // Q tile cp.async (both splits), folded into group 0
    {
        const char* s0 = (const char*)(qh_g + (size_t)(b * SEQ + qt * 128) * NEMB + h * 128);
        const char* s1 = (const char*)(ql_g + (size_t)(b * SEQ + qt * 128) * NEMB + h * 128);
        #pragma unroll
        for (int i = 0; i < 8; i++) {
            int c = tid + i * 256;
            int row = c >> 4, off = (c & 15) * 16;
            CP_ASYNC16(sb + row * QSTR + off,         s0 + (size_t)row * (NEMB * 2) + off);
            CP_ASYNC16(sb + SM_QB + row * QSTR + off, s1 + (size_t)row * (NEMB * 2) + off);
        }
    }
    auto issue = [&](int kt, int st) {
        uint32_t kb = sb + SM_K + st * KSTAGE;
        uint32_t vb = sb + SM_V + st * VSTAGE;
        const char* ksh = (const char*)(kh_g + (size_t)(b * SEQ + kt * 32) * HD);
        const char* ksl = (const char*)(kl_g + (size_t)(b * SEQ + kt * 32) * HD);
        #pragma unroll
        for (int i = 0; i < 2; i++) {
            int c = tid + i * 256;
            int row = c >> 4, off = (c & 15) * 16;
            CP_ASYNC16(kb + row * KSTR + off,        ksh + (size_t)row * 256 + off);
            CP_ASYNC16(kb + KBUF + row * KSTR + off, ksl + (size_t)row * 256 + off);
        }
        const char* vsh = (const char*)(vth_g + (size_t)b * HD * SEQ + kt * 32);
        const char* vsl = (const char*)(vtl_g + (size_t)b * HD * SEQ + kt * 32);
        #pragma unroll
        for (int i = 0; i < 2; i++) {
            int c = tid + i * 256;
            int row = c >> 2, off = (c & 3) * 16;
            CP_ASYNC16(vb + row * VSTR + off,        vsh + (size_t)row * (SEQ * 2) + off);
            CP_ASYNC16(vb + VBUF + row * VSTR + off, vsl + (size_t)row * (SEQ * 2) + off);
        }
        CP_COMMIT();
    };
    issue(0, 0);
    issue(1, 1);

    float oacc[16][4] = {};
    float lsum0 = 0.f, lsum1 = 0.f;
    const float SC2 = 0.08838834764831845f * 1.44269504088896f;  // scale * log2(e)

    const uint32_t qah = sb + (warp * 16 + lr) * QSTR + lc * 16;
    const uint32_t qal = qah + SM_QB;

    const int NKT = SEQ / 32;
    int stg = 0;
    for (int kt = 0; kt < NKT; kt++) {
        if (kt == NKT - 1) { CP_WAIT0(); } else { CP_WAIT1(); }
        __syncthreads();
        if (kt + 2 < NKT) issue(kt + 2, stg == 0 ? 2 : stg - 1);

        const uint32_t kb = sb + SM_K + stg * KSTAGE;
        const uint32_t vb = sb + SM_V + stg * VSTAGE;

        // ---- S = Q @ K^T (split: hh + hl + lh) ----
        float sacc[4][4] = {};
        #pragma unroll
        for (int kh = 0; kh < 8; kh++) {
            uint32_t qfh[4], qfl[4], kfh[2][4], kfl[2][4];
            LDSM_X4(qfh, qah + kh * 32);
            LDSM_X4(qfl, qal + kh * 32);
            #pragma unroll
            for (int g = 0; g < 2; g++) {
                uint32_t ka = kb + (g * 16 + lr) * KSTR + kh * 32 + lc * 16;
                LDSM_X4(kfh[g], ka);
                LDSM_X4(kfl[g], ka + KBUF);
            }
            #pragma unroll
            for (int na = 0; na < 4; na++) {
                const int g = na >> 1, hi = na & 1;
                mma_bf16(sacc[na], qfh, kfh[g][hi], kfh[g][hi + 2]);
                mma_bf16(sacc[na], qfh, kfl[g][hi], kfl[g][hi + 2]);
                mma_bf16(sacc[na], qfl, kfh[g][hi], kfh[g][hi + 2]);
            }
        }

        // ---- P = exp(S*scale); accumulate row sums; build split A-frags ----
        uint32_t pah[2][4], pal[2][4];
        float l0 = 0.f, l1 = 0.f;
        #pragma unroll
        for (int na = 0; na < 4; na++) {
            float p0 = exp2f(sacc[na][0] * SC2);
            float p1 = exp2f(sacc[na][1] * SC2);
            float p2 = exp2f(sacc[na][2] * SC2);
            float p3 = exp2f(sacc[na][3] * SC2);
            l0 += p0 + p1; l1 += p2 + p3;
            const int t = na >> 1, half = na & 1;
            __nv_bfloat16 h0 = __float2bfloat16(p0), h1 = __float2bfloat16(p1);
            __nv_bfloat16 h2 = __float2bfloat16(p2), h3 = __float2bfloat16(p3);
            pah[t][half * 2 + 0] = pack_bf16(__bfloat162float(h0), __bfloat162float(h1));
            pah[t][half * 2 + 1] = pack_bf16(__bfloat162float(h2), __bfloat162float(h3));
            pal[t][half * 2 + 0] = pack_bf16(p0 - __bfloat162float(h0), p1 - __bfloat162float(h1));
            pal[t][half * 2 + 1] = pack_bf16(p2 - __bfloat162float(h2), p3 - __bfloat162float(h3));
        }
        l0 += __shfl_xor_sync(0xffffffffu, l0, 1);
        l0 += __shfl_xor_sync(0xffffffffu, l0, 2);
        l1 += __shfl_xor_sync(0xffffffffu, l1, 1);
        l1 += __shfl_xor_sync(0xffffffffu, l1, 2);
        lsum0 += l0; lsum1 += l1;

        // ---- O += P @ V (split: hh + hl + lh) ----
        #pragma unroll
        for (int nb8 = 0; nb8 < 8; nb8++) {
            uint32_t vfh[2][4], vfl[2][4];
            #pragma unroll
            for (int ka = 0; ka < 2; ka++) {
                uint32_t va = vb + (nb8 * 16 + lr) * VSTR + ka * 32 + lc * 16;
                LDSM_X4(vfh[ka], va);
                LDSM_X4(vfl[ka], va + VBUF);
            }
            #pragma unroll
            for (int ns = 0; ns < 2; ns++) {
                const int n = nb8 * 2 + ns;
                #pragma unroll
                for (int t = 0; t < 2; t++) {
                    mma_bf16(oacc[n], pah[t], vfh[t][ns], vfh[t][ns + 2]);
                    mma_bf16(oacc[n], pah[t], vfl[t][ns], vfl[t][ns + 2]);
                    mma_bf16(oacc[n], pal[t], vfh[t][ns], vfh[t][ns + 2]);
                }
            }
        }
        stg = (stg == 2) ? 0 : stg + 1;
    }

    // ---- epilogue: normalize, split to bf16 hi/lo ----
    const float inv0 = 1.f / lsum0, inv1 = 1.f / lsum1;
    const size_t row0 = (size_t)(b * SEQ + qt * 128 + warp * 16 + gr);
    #pragma unroll
    for (int n = 0; n < 16; n++) {
        const size_t col = (size_t)h * 128 + n * 8 + gc;
        float v0 = oacc[n][0] * inv0, v1 = oacc[n][1] * inv0;
        float v2 = oacc[n][2] * inv1, v3 = oacc[n][3] * inv1;
        __nv_bfloat16 h0 = __float2bfloat16(v0), h1 = __float2bfloat16(v1);
        __nv_bfloat16 h2 = __float2bfloat16(v2), h3 = __float2bfloat16(v3);
        *(uint32_t*)&oh_g[row0 * NEMB + col] = pack_bf16(__bfloat162float(h0), __bfloat162float(h1));
        *(uint32_t*)&ol_g[row0 * NEMB + col] = pack_bf16(v0 - __bfloat162float(h0), v1 - __bfloat162float(h1));
        *(uint32_t*)&oh_g[(row0 + 8) * NEMB + col] = pack_bf16(__bfloat162float(h2), __bfloat162float(h3));
        *(uint32_t*)&ol_g[(row0 + 8) * NEMB + col] = pack_bf16(v2 - __bfloat162float(h2), v3 - __bfloat162float(h3));
    }
}

// ---------------------------------------------------------------------------
// fp32 -> bf16 hi/lo split
// ---------------------------------------------------------------------------
__global__ void split_kernel(const float* __restrict__ in,
                             __nv_bfloat16* __restrict__ hi,
                             __nv_bfloat16* __restrict__ lo, int n) {
    int i = (blockIdx.x * blockDim.x + threadIdx.x) * 4;
    if (i >= n) return;
    float4 v = *(const float4*)(in + i);
    __nv_bfloat16 h0 = __float2bfloat16(v.x), h1 = __float2bfloat16(v.y);
    __nv_bfloat16 h2 = __float2bfloat16(v.z), h3 = __float2bfloat16(v.w);
    __nv_bfloat162* H = (__nv_bfloat162*)(hi + i);
    __nv_bfloat162* L = (__nv_bfloat162*)(lo + i);
    H[0] = __nv_bfloat162(h0, h1); H[1] = __nv_bfloat162(h2, h3);
    L[0] = __nv_bfloat162(__float2bfloat16(v.x - __bfloat162float(h0)),
                          __float2bfloat16(v.y - __bfloat162float(h1)));
    L[1] = __nv_bfloat162(__float2bfloat16(v.z - __bfloat162float(h2)),
                          __float2bfloat16(v.w - __bfloat162float(h3)));
}

// ---------------------------------------------------------------------------
// transpose + split: w[K][N] fp32 -> hi/lo[N][K] bf16
// ---------------------------------------------------------------------------
__global__ void transpose_split_kernel(const float* __restrict__ w,
                                       __nv_bfloat16* __restrict__ hi,
                                       __nv_bfloat16* __restrict__ lo,
                                       int K, int N) {
    __shared__ float t[32][33];
    int n0 = blockIdx.x * 32, k0 = blockIdx.y * 32;
    int tx = threadIdx.x, ty = threadIdx.y;
    #pragma unroll
    for (int r = ty; r < 32; r += 8)
        t[r][tx] = w[(size_t)(k0 + r) * N + n0 + tx];
    __syncthreads();
    #pragma unroll
    for (int r = ty; r < 32; r += 8) {
        float v = t[tx][r];
        __nv_bfloat16 h = __float2bfloat16(v);
        size_t o = (size_t)(n0 + r) * K + k0 + tx;
        hi[o] = h;
        lo[o] = __float2bfloat16(v - __bfloat162float(h));
    }
}

// ---------------------------------------------------------------------------
// RoPE + split q,k -> bf16 hi/lo
// ---------------------------------------------------------------------------
__global__ void rope_split_kernel(const float* __restrict__ qkv,
                                  __nv_bfloat16* __restrict__ qh, __nv_bfloat16* __restrict__ ql,
                                  __nv_bfloat16* __restrict__ kh, __nv_bfloat16* __restrict__ kl) {
    const int total = ROWS * 17 * 64;
    int idx = blockIdx.x * blockDim.x + threadIdx.x;
    if (idx >= total) return;
    int i    = idx & 63;
    int head = (idx >> 6) % 17;
    int row  = idx / (17 * 64);
    int t    = row & (SEQ - 1);
    int off  = (head < 16) ? head * HD : 2048;
    const float* p = qkv + (size_t)row * QKV_COLS + off;
    float freq = expf(-(4.0f * (float)i + 1.0f) * (9.210340371976184f / 128.0f));
    float ang = (float)t * freq;
    float c = cosf(ang), s = sinf(ang);
    float x1 = p[i], x2 = p[i + 64];
    float y1 = x1 * c - x2 * s;
    float y2 = x2 * c + x1 * s;
    __nv_bfloat16 h1 = __float2bfloat16(y1), h2 = __float2bfloat16(y2);
    if (head < 16) {
        size_t o = (size_t)row * NEMB + head * HD;
        qh[o + i]      = h1;  ql[o + i]      = __float2bfloat16(y1 - __bfloat162float(h1));
        qh[o + i + 64] = h2;  ql[o + i + 64] = __float2bfloat16(y2 - __bfloat162float(h2));
    } else {
        size_t o = (size_t)row * HD;
        kh[o + i]      = h1;  kl[o + i]      = __float2bfloat16(y1 - __bfloat162float(h1));
        kh[o + i + 64] = h2;  kl[o + i + 64] = __float2bfloat16(y2 - __bfloat162float(h2));
    }
}

// ---------------------------------------------------------------------------
// V transpose + split: qkv[b*SEQ+t][2176+d] -> vt[b][d][t] bf16 hi/lo
// ---------------------------------------------------------------------------
__global__ void vt_split_kernel(const float* __restrict__ qkv,
                                __nv_bfloat16* __restrict__ vth,
                                __nv_bfloat16* __restrict__ vtl) {
    __shared__ float tile[32][33];
    int t0 = blockIdx.x * 32, d0 = blockIdx.y * 32, b = blockIdx.z;
    int tx = threadIdx.x, ty = threadIdx.y;
    #pragma unroll
    for (int r = ty; r < 32; r += 8)
        tile[r][tx] = qkv[(size_t)(b * SEQ + t0 + r) * QKV_COLS + 2176 + d0 + tx];
    __syncthreads();
    #pragma unroll
    for (int r = ty; r < 32; r += 8) {
        float v = tile[tx][r];
        __nv_bfloat16 h = __float2bfloat16(v);
        size_t o = ((size_t)b * HD + d0 + r) * SEQ + t0 + tx;
        vth[o] = h;
        vtl[o] = __float2bfloat16(v - __bfloat162float(h));
    }
}

// ---------------------------------------------------------------------------
extern "C" void kernel_launch(void* const* d_in, const int* in_sizes, int n_in,
                              void* d_out, int out_size) {
    const float* x      = (const float*)d_in[0];
    const float* w_attn = (const float*)d_in[1];
    const float* w_out  = (const float*)d_in[2];
    float* out = (float*)d_out;

    float *qkv;
    __nv_bfloat16 *xhi, *xlo, *wath, *watl, *woth, *wotl, *atth, *attl;
    __nv_bfloat16 *qhi, *qlo, *khi, *klo, *vth, *vtl;
    cudaGetSymbolAddress((void**)&qkv,  g_qkv);
    cudaGetSymbolAddress((void**)&xhi,  g_x_hi);
    cudaGetSymbolAddress((void**)&xlo,  g_x_lo);
    cudaGetSymbolAddress((void**)&wath, g_wat_hi);
    cudaGetSymbolAddress((void**)&watl, g_wat_lo);
    cudaGetSymbolAddress((void**)&woth, g_wot_hi);
    cudaGetSymbolAddress((void**)&wotl, g_wot_lo);
    cudaGetSymbolAddress((void**)&atth, g_att_hi);
    cudaGetSymbolAddress((void**)&attl, g_att_lo);
    cudaGetSymbolAddress((void**)&qhi,  g_q_hi);
    cudaGetSymbolAddress((void**)&qlo,  g_q_lo);
    cudaGetSymbolAddress((void**)&khi,  g_k_hi);
    cudaGetSymbolAddress((void**)&klo,  g_k_lo);
    cudaGetSymbolAddress((void**)&vth,  g_vt_hi);
    cudaGetSymbolAddress((void**)&vtl,  g_vt_lo);

    cudaFuncSetAttribute(hmma_gemm_kernel, cudaFuncAttributeMaxDynamicSharedMemorySize, GEMM_SMEM);
    cudaFuncSetAttribute(hmma_attn_kernel, cudaFuncAttributeMaxDynamicSharedMemorySize, ATT_SMEM);

    // 0) precision splits
    int nx = ROWS * NEMB;
    split_kernel<<<nx / (4 * 256), 256>>>(x, xhi, xlo, nx);
    transpose_split_kernel<<<dim3(QKV_COLS / 32, NEMB / 32), dim3(32, 8)>>>(w_attn, wath, watl, NEMB, QKV_COLS);
    transpose_split_kernel<<<dim3(NEMB / 32, NEMB / 32), dim3(32, 8)>>>(w_out, woth, wotl, NEMB, NEMB);

    // 1) qkv = x @ w_attn  (HMMA split-bf16)
    hmma_gemm_kernel<<<dim3(QKV_COLS / 128, ROWS / 128), 256, GEMM_SMEM>>>(
        xhi, xlo, wath, watl, qkv, ROWS, QKV_COLS, NEMB);

    // 2) RoPE + split q,k ; transpose + split v
    int rope_total = ROWS * 17 * 64;
    rope_split_kernel<<<(rope_total + 255) / 256, 256>>>(qkv, qhi, qlo, khi, klo);
    vt_split_kernel<<<dim3(SEQ / 32, HD / 32, BATCH), dim3(32, 8)>>>(qkv, vth, vtl);

    // 3) HMMA flash attention -> att hi/lo
    hmma_attn_kernel<<<dim3(SEQ / 128, NHEAD, BATCH), 256, ATT_SMEM>>>(
        qhi, qlo, khi, klo, vth, vtl, atth, attl);

    // 4) out = att @ w_out  (HMMA split-bf16)
    hmma_gemm_kernel<<<dim3(NEMB / 128, ROWS / 128), 256, GEMM_SMEM>>>(
        atth, attl, woth, wotl, out, ROWS, NEMB, NEMB);
}

// round 12
// speedup vs baseline: 1.1087x; 1.1087x over previous
#include <cuda_runtime.h>
#include <cuda_bf16.h>
#include <cstdint>
#include <math.h>

#define BATCH   2
#define SEQ     2048
#define NEMB    2048
#define NHEAD   16
#define HD      128
#define QKV_COLS 2304          // (16+2)*128
#define ROWS    (BATCH*SEQ)    // 4096

// ---------------- scratch (no cudaMalloc allowed) ----------------
__device__ float g_qkv[ROWS * QKV_COLS];
__device__ __nv_bfloat16 g_x_hi[ROWS * NEMB];
__device__ __nv_bfloat16 g_x_lo[ROWS * NEMB];
__device__ __nv_bfloat16 g_wat_hi[QKV_COLS * NEMB];   // transposed [N][K]
__device__ __nv_bfloat16 g_wat_lo[QKV_COLS * NEMB];
__device__ __nv_bfloat16 g_wot_hi[NEMB * NEMB];       // transposed [N][K]
__device__ __nv_bfloat16 g_wot_lo[NEMB * NEMB];
__device__ __nv_bfloat16 g_att_hi[ROWS * NEMB];
__device__ __nv_bfloat16 g_att_lo[ROWS * NEMB];
__device__ __nv_bfloat16 g_q_hi[ROWS * NEMB];         // post-RoPE q
__device__ __nv_bfloat16 g_q_lo[ROWS * NEMB];
__device__ __nv_bfloat16 g_k_hi[ROWS * HD];           // post-RoPE k [b*SEQ+t][128]
__device__ __nv_bfloat16 g_k_lo[ROWS * HD];
__device__ __nv_bfloat16 g_vt_hi[BATCH * HD * SEQ];   // v transposed [b][d][t]
__device__ __nv_bfloat16 g_vt_lo[BATCH * HD * SEQ];

// ---------------- PTX helpers (baseline ISA only: sm_80-class) ----------------
__device__ __forceinline__ uint32_t smem_u32(const void* p) {
    uint32_t a;
    asm("{ .reg .u64 t; cvta.to.shared.u64 t, %1; cvt.u32.u64 %0, t; }" : "=r"(a) : "l"(p));
    return a;
}
#define CP_ASYNC16(s, g) \
    asm volatile("cp.async.cg.shared.global [%0], [%1], 16;" :: "r"(s), "l"(g) : "memory")
#define CP_COMMIT() asm volatile("cp.async.commit_group;" ::: "memory")
#define CP_WAIT1()  asm volatile("cp.async.wait_group 1;" ::: "memory")
#define CP_WAIT0()  asm volatile("cp.async.wait_group 0;" ::: "memory")
#define LDSM_X4(r, a) \
    asm volatile("ldmatrix.sync.aligned.m8n8.x4.shared.b16 {%0,%1,%2,%3}, [%4];" \
        : "=r"((r)[0]), "=r"((r)[1]), "=r"((r)[2]), "=r"((r)[3]) : "r"(a))

__device__ __forceinline__ void mma_bf16(float* d, const uint32_t* a, uint32_t b0, uint32_t b1) {
    asm volatile(
        "mma.sync.aligned.m16n8k16.row.col.f32.bf16.bf16.f32 "
        "{%0,%1,%2,%3}, {%4,%5,%6,%7}, {%8,%9}, {%0,%1,%2,%3};"
        : "+f"(d[0]), "+f"(d[1]), "+f"(d[2]), "+f"(d[3])
        : "r"(a[0]), "r"(a[1]), "r"(a[2]), "r"(a[3]), "r"(b0), "r"(b1));
}
__device__ __forceinline__ uint32_t pack_bf16(float x, float y) {
    __nv_bfloat162 t = __floats2bfloat162_rn(x, y);
    return *(uint32_t*)&t;
}

// ---------------------------------------------------------------------------
// HMMA split-bf16 GEMM: C[M,N] fp32 = (Ah+Al)[M,K] @ (Bh+Bl)[N,K]^T
// 128x128 CTA tile, k-chunk 32, 3-stage cp.async, ONE sync per chunk,
// XOR-swizzled 64B rows (no padding) so 3 stages fit in 96KB -> 2 CTAs/SM.
// Swizzle: phys_col16 = col16 ^ ((row>>1)&3). Store & load use same formula.
// ---------------------------------------------------------------------------
#define GBUF_B   8192                  // 128 rows x 64B, one logical tile
#define GSTAGE_B (4 * GBUF_B)          // Ah, Al, Bh, Bl = 32768
#define GEMM_SMEM (3 * GSTAGE_B)       // 98304 -> 2 CTAs/SM

__global__ __launch_bounds__(256, 2) void hmma_gemm_kernel(
    const __nv_bfloat16* __restrict__ Ah, const __nv_bfloat16* __restrict__ Al,
    const __nv_bfloat16* __restrict__ Bh, const __nv_bfloat16* __restrict__ Bl,
    float* __restrict__ C, int M, int N, int K)
{
    extern __shared__ char smem[];
    const uint32_t sb = smem_u32(smem);
    const int tid  = threadIdx.x;
    const int lane = tid & 31;
    const int warp = tid >> 5;
    const int m0 = blockIdx.y * 128, n0 = blockIdx.x * 128;
    const int wm = (warp >> 2) * 64, wn = (warp & 3) * 32;

    // ---- copy mapping: row = tid>>1, two 16B cols per buffer ----
    const int crow = tid >> 1;
    const int ccol = (tid & 1) * 2;              // logical col16: 0 or 2
    const int csw  = (crow >> 1) & 3;
    const uint32_t cd0 = crow * 64 + ((ccol    ) ^ csw) * 16;
    const uint32_t cd1 = crow * 64 + ((ccol + 1) ^ csw) * 16;
    const char* gsrc[4];
    gsrc[0] = (const char*)(Ah + (size_t)(m0 + crow) * K);
    gsrc[1] = (const char*)(Al + (size_t)(m0 + crow) * K);
    gsrc[2] = (const char*)(Bh + (size_t)(n0 + crow) * K);
    gsrc[3] = (const char*)(Bl + (size_t)(n0 + crow) * K);

    const int nch = K / 32;
    float acc[4][4][4] = {};
    const int lr = lane & 15;
    const int lc = lane >> 4;

    auto issue = [&](int ch, int st) {
        const uint32_t so = sb + st * GSTAGE_B;
        #pragma unroll
        for (int b = 0; b < 4; b++) {
            const char* g = gsrc[b] + (size_t)ch * 64 + ccol * 16;
            uint32_t s0 = so + b * GBUF_B;
            CP_ASYNC16(s0 + cd0, g);
            CP_ASYNC16(s0 + cd1, g + 16);
        }
        CP_COMMIT();
    };

    // ldsm row bases + swizzle keys (stage-independent parts)
    uint32_t arow[4], asw[4], brow[2], bsw[2];
    #pragma unroll
    for (int ma = 0; ma < 4; ma++) {
        int r = wm + ma * 16 + lr;
        arow[ma] = r * 64; asw[ma] = (r >> 1) & 3;
    }
    #pragma unroll
    for (int ng = 0; ng < 2; ng++) {
        int r = wn + ng * 16 + lr;
        brow[ng] = r * 64; bsw[ng] = (r >> 1) & 3;
    }

    issue(0, 0);
    issue(1, 1);
    int stg = 0;
    for (int ch = 0; ch < nch; ch++) {
        if (ch == nch - 1) { CP_WAIT0(); } else { CP_WAIT1(); }
        __syncthreads();
        if (ch + 2 < nch) issue(ch + 2, stg == 0 ? 2 : stg - 1);

        const uint32_t stage = sb + stg * GSTAGE_B;

        #pragma unroll
        for (int kh = 0; kh < 2; kh++) {
            const uint32_t col = kh * 2 + lc;    // logical col16 0..3
            uint32_t ah[4][4], al[4][4], bh[2][4], bl[2][4];
            #pragma unroll
            for (int ma = 0; ma < 4; ma++) {
                uint32_t ad = stage + arow[ma] + ((col ^ asw[ma]) << 4);
                LDSM_X4(ah[ma], ad);
                LDSM_X4(al[ma], ad + GBUF_B);
            }
            #pragma unroll
            for (int ng = 0; ng < 2; ng++) {
                uint32_t bd = stage + 2 * GBUF_B + brow[ng] + ((col ^ bsw[ng]) << 4);
                LDSM_X4(bh[ng], bd);
                LDSM_X4(bl[ng], bd + GBUF_B);
            }
            #pragma unroll
            for (int ma = 0; ma < 4; ma++)
                #pragma unroll
                for (int na = 0; na < 4; na++) {
                    const int ng = na >> 1, hi = na & 1;
                    mma_bf16(acc[ma][na], ah[ma], bh[ng][hi], bh[ng][hi + 2]);
                    mma_bf16(acc[ma][na], ah[ma], bl[ng][hi], bl[ng][hi + 2]);
                    mma_bf16(acc[ma][na], al[ma], bh[ng][hi], bh[ng][hi + 2]);
                }
        }
        stg = (stg == 2) ? 0 : stg + 1;
    }

    const int gr = lane >> 2, gc = (lane & 3) * 2;
    #pragma unroll
    for (int ma = 0; ma < 4; ma++) {
        #pragma unroll
        for (int na = 0; na < 4; na++) {
            size_t r = (size_t)(m0 + wm + ma * 16 + gr);
            size_t c = (size_t)(n0 + wn + na * 8 + gc);
            *(float2*)&C[r * N + c]       = make_float2(acc[ma][na][0], acc[ma][na][1]);
            *(float2*)&C[(r + 8) * N + c] = make_float2(acc[ma][na][2], acc[ma][na][3]);
        }
    }
}

// ---------------------------------------------------------------------------
// HMMA flash attention (no-max softmax), split-bf16, 2-stage K/V pipeline
// (reverted to the R9-proven version; 1 CTA/SM is smem-forced here anyway).
// Block = (128 q rows, head, batch), 8 warps x (16 rows x 32 keys).
// ---------------------------------------------------------------------------
#define QSTR 272
#define KSTR 272
#define VSTR 80
#define SM_QB  (128*QSTR)           // per-split Q bytes (34816)
#define SM_K   (2*SM_QB)            // 69632
#define KBUF   (32*KSTR)            // 8704
#define KSTAGE (2*KBUF)             // 17408
#define SM_V   (SM_K + 2*KSTAGE)    // 104448
#define VBUF   (128*VSTR)           // 10240
#define VSTAGE (2*VBUF)             // 20480
#define ATT_SMEM (SM_V + 2*VSTAGE)  // 145408

__global__ __launch_bounds__(256, 1) void hmma_attn_kernel(
    const __nv_bfloat16* __restrict__ qh_g, const __nv_bfloat16* __restrict__ ql_g,
    const __nv_bfloat16* __restrict__ kh_g, const __nv_bfloat16* __restrict__ kl_g,
    const __nv_bfloat16* __restrict__ vth_g, const __nv_bfloat16* __restrict__ vtl_g,
    __nv_bfloat16* __restrict__ oh_g, __nv_bfloat16* __restrict__ ol_g)
{
    extern __shared__ char smem[];
    const uint32_t sb = smem_u32(smem);
    const int qt = blockIdx.x, h = blockIdx.y, b = blockIdx.z;
    const int tid = threadIdx.x, lane = tid & 31, warp = tid >> 5;
    const int lr = lane & 15, lc = lane >> 4;
    const int gr = lane >> 2, gc = (lane & 3) * 2;

    // Q tile cp.async (both splits), folded into group 0
    {
        const char* s0 = (const char*)(qh_g + (size_t)(b * SEQ + qt * 128) * NEMB + h * 128);
        const char* s1 = (const char*)(ql_g + (size_t)(b * SEQ + qt * 128) * NEMB + h * 128);
        #pragma unroll
        for (int i = 0; i < 8; i++) {
            int c = tid + i * 256;
            int row = c >> 4, off = (c & 15) * 16;
            CP_ASYNC16(sb + row * QSTR + off,         s0 + (size_t)row * (NEMB * 2) + off);
            CP_ASYNC16(sb + SM_QB + row * QSTR + off, s1 + (size_t)row * (NEMB * 2) + off);
        }
    }
    auto issue = [&](int kt) {
        uint32_t kb = sb + SM_K + (kt & 1) * KSTAGE;
        uint32_t vb = sb + SM_V + (kt & 1) * VSTAGE;
        const char* ksh = (const char*)(kh_g + (size_t)(b * SEQ + kt * 32) * HD);
        const char* ksl = (const char*)(kl_g + (size_t)(b * SEQ + kt * 32) * HD);
        #pragma unroll
        for (int i = 0; i < 2; i++) {
            int c = tid + i * 256;
            int row = c >> 4, off = (c & 15) * 16;
            CP_ASYNC16(kb + row * KSTR + off,        ksh + (size_t)row * 256 + off);
            CP_ASYNC16(kb + KBUF + row * KSTR + off, ksl + (size_t)row * 256 + off);
        }
        const char* vsh = (const char*)(vth_g + (size_t)b * HD * SEQ + kt * 32);
        const char* vsl = (const char*)(vtl_g + (size_t)b * HD * SEQ + kt * 32);
        #pragma unroll
        for (int i = 0; i < 2; i++) {
            int c = tid + i * 256;
            int row = c >> 2, off = (c & 3) * 16;
            CP_ASYNC16(vb + row * VSTR + off,        vsh + (size_t)row * (SEQ * 2) + off);
            CP_ASYNC16(vb + VBUF + row * VSTR + off, vsl + (size_t)row * (SEQ * 2) + off);
        }
    };
    issue(0); CP_COMMIT();
    issue(1); CP_COMMIT();

    float oacc[16][4] = {};
    float lsum0 = 0.f, lsum1 = 0.f;
    const float SC2 = 0.08838834764831845f * 1.44269504088896f;  // scale * log2(e)

    const uint32_t qah = sb + (warp * 16 + lr) * QSTR + lc * 16;
    const uint32_t qal = qah + SM_QB;

    const int NKT = SEQ / 32;
    for (int kt = 0; kt < NKT; kt++) {
        if (kt == NKT - 1) { CP_WAIT0(); } else { CP_WAIT1(); }
        __syncthreads();
        const uint32_t kb = sb + SM_K + (kt & 1) * KSTAGE;
        const uint32_t vb = sb + SM_V + (kt & 1) * VSTAGE;

        // ---- S = Q @ K^T (split: hh + hl + lh) ----
        float sacc[4][4] = {};
        #pragma unroll
        for (int kh = 0; kh < 8; kh++) {
            uint32_t qfh[4], qfl[4], kfh[2][4], kfl[2][4];
            LDSM_X4(qfh, qah + kh * 32);
            LDSM_X4(qfl, qal + kh * 32);
            #pragma unroll
            for (int g = 0; g < 2; g++) {
                uint32_t ka = kb + (g * 16 + lr) * KSTR + kh * 32 + lc * 16;
                LDSM_X4(kfh[g], ka);
                LDSM_X4(kfl[g], ka + KBUF);
            }
            #pragma unroll
            for (int na = 0; na < 4; na++) {
                const int g = na >> 1, hi = na & 1;
                mma_bf16(sacc[na], qfh, kfh[g][hi], kfh[g][hi + 2]);
                mma_bf16(sacc[na], qfh, kfl[g][hi], kfl[g][hi + 2]);
                mma_bf16(sacc[na], qfl, kfh[g][hi], kfh[g][hi + 2]);
            }
        }

        // ---- P = exp(S*scale); accumulate row sums; build split A-frags ----
        uint32_t pah[2][4], pal[2][4];
        float l0 = 0.f, l1 = 0.f;
        #pragma unroll
        for (int na = 0; na < 4; na++) {
            float p0 = exp2f(sacc[na][0] * SC2);
            float p1 = exp2f(sacc[na][1] * SC2);
            float p2 = exp2f(sacc[na][2] * SC2);
            float p3 = exp2f(sacc[na][3] * SC2);
            l0 += p0 + p1; l1 += p2 + p3;
            const int t = na >> 1, half = na & 1;
            __nv_bfloat16 h0 = __float2bfloat16(p0), h1 = __float2bfloat16(p1);
            __nv_bfloat16 h2 = __float2bfloat16(p2), h3 = __float2bfloat16(p3);
            pah[t][half * 2 + 0] = pack_bf16(__bfloat162float(h0), __bfloat162float(h1));
            pah[t][half * 2 + 1] = pack_bf16(__bfloat162float(h2), __bfloat162float(h3));
            pal[t][half * 2 + 0] = pack_bf16(p0 - __bfloat162float(h0), p1 - __bfloat162float(h1));
            pal[t][half * 2 + 1] = pack_bf16(p2 - __bfloat162float(h2), p3 - __bfloat162float(h3));
        }
        l0 += __shfl_xor_sync(0xffffffffu, l0, 1);
        l0 += __shfl_xor_sync(0xffffffffu, l0, 2);
        l1 += __shfl_xor_sync(0xffffffffu, l1, 1);
        l1 += __shfl_xor_sync(0xffffffffu, l1, 2);
        lsum0 += l0; lsum1 += l1;

        // ---- O += P @ V (split: hh + hl + lh) ----
        #pragma unroll
        for (int nb8 = 0; nb8 < 8; nb8++) {
            uint32_t vfh[2][4], vfl[2][4];
            #pragma unroll
            for (int ka = 0; ka < 2; ka++) {
                uint32_t va = vb + (nb8 * 16 + lr) * VSTR + ka * 32 + lc * 16;
                LDSM_X4(vfh[ka], va);
                LDSM_X4(vfl[ka], va + VBUF);
            }
            #pragma unroll
            for (int ns = 0; ns < 2; ns++) {
                const int n = nb8 * 2 + ns;
                #pragma unroll
                for (int t = 0; t < 2; t++) {
                    mma_bf16(oacc[n], pah[t], vfh[t][ns], vfh[t][ns + 2]);
                    mma_bf16(oacc[n], pah[t], vfl[t][ns], vfl[t][ns + 2]);
                    mma_bf16(oacc[n], pal[t], vfh[t][ns], vfh[t][ns + 2]);
                }
            }
        }
        __syncthreads();
        if (kt + 2 < NKT) { issue(kt + 2); CP_COMMIT(); }
    }

    // ---- epilogue: normalize, split to bf16 hi/lo ----
    const float inv0 = 1.f / lsum0, inv1 = 1.f / lsum1;
    const size_t row0 = (size_t)(b * SEQ + qt * 128 + warp * 16 + gr);
    #pragma unroll
    for (int n = 0; n < 16; n++) {
        const size_t col = (size_t)h * 128 + n * 8 + gc;
        float v0 = oacc[n][0] * inv0, v1 = oacc[n][1] * inv0;
        float v2 = oacc[n][2] * inv1, v3 = oacc[n][3] * inv1;
        __nv_bfloat16 h0 = __float2bfloat16(v0), h1 = __float2bfloat16(v1);
        __nv_bfloat16 h2 = __float2bfloat16(v2), h3 = __float2bfloat16(v3);
        *(uint32_t*)&oh_g[row0 * NEMB + col] = pack_bf16(__bfloat162float(h0), __bfloat162float(h1));
        *(uint32_t*)&ol_g[row0 * NEMB + col] = pack_bf16(v0 - __bfloat162float(h0), v1 - __bfloat162float(h1));
        *(uint32_t*)&oh_g[(row0 + 8) * NEMB + col] = pack_bf16(__bfloat162float(h2), __bfloat162float(h3));
        *(uint32_t*)&ol_g[(row0 + 8) * NEMB + col] = pack_bf16(v2 - __bfloat162float(h2), v3 - __bfloat162float(h3));
    }
}

// ---------------------------------------------------------------------------
// fp32 -> bf16 hi/lo split
// ---------------------------------------------------------------------------
__global__ void split_kernel(const float* __restrict__ in,
                             __nv_bfloat16* __restrict__ hi,
                             __nv_bfloat16* __restrict__ lo, int n) {
    int i = (blockIdx.x * blockDim.x + threadIdx.x) * 4;
    if (i >= n) return;
    float4 v = *(const float4*)(in + i);
    __nv_bfloat16 h0 = __float2bfloat16(v.x), h1 = __float2bfloat16(v.y);
    __nv_bfloat16 h2 = __float2bfloat16(v.z), h3 = __float2bfloat16(v.w);
    __nv_bfloat162* H = (__nv_bfloat162*)(hi + i);
    __nv_bfloat162* L = (__nv_bfloat162*)(lo + i);
    H[0] = __nv_bfloat162(h0, h1); H[1] = __nv_bfloat162(h2, h3);
    L[0] = __nv_bfloat162(__float2bfloat16(v.x - __bfloat162float(h0)),
                          __float2bfloat16(v.y - __bfloat162float(h1)));
    L[1] = __nv_bfloat162(__float2bfloat16(v.z - __bfloat162float(h2)),
                          __float2bfloat16(v.w - __bfloat162float(h3)));
}

// ---------------------------------------------------------------------------
// transpose + split: w[K][N] fp32 -> hi/lo[N][K] bf16
// ---------------------------------------------------------------------------
__global__ void transpose_split_kernel(const float* __restrict__ w,
                                       __nv_bfloat16* __restrict__ hi,
                                       __nv_bfloat16* __restrict__ lo,
                                       int K, int N) {
    __shared__ float t[32][33];
    int n0 = blockIdx.x * 32, k0 = blockIdx.y * 32;
    int tx = threadIdx.x, ty = threadIdx.y;
    #pragma unroll
    for (int r = ty; r < 32; r += 8)
        t[r][tx] = w[(size_t)(k0 + r) * N + n0 + tx];
    __syncthreads();
    #pragma unroll
    for (int r = ty; r < 32; r += 8) {
        float v = t[tx][r];
        __nv_bfloat16 h = __float2bfloat16(v);
        size_t o = (size_t)(n0 + r) * K + k0 + tx;
        hi[o] = h;
        lo[o] = __float2bfloat16(v - __bfloat162float(h));
    }
}

// ---------------------------------------------------------------------------
// RoPE + split q,k -> bf16 hi/lo
// ---------------------------------------------------------------------------
__global__ void rope_split_kernel(const float* __restrict__ qkv,
                                  __nv_bfloat16* __restrict__ qh, __nv_bfloat16* __restrict__ ql,
                                  __nv_bfloat16* __restrict__ kh, __nv_bfloat16* __restrict__ kl) {
    const int total = ROWS * 17 * 64;
    int idx = blockIdx.x * blockDim.x + threadIdx.x;
    if (idx >= total) return;
    int i    = idx & 63;
    int head = (idx >> 6) % 17;
    int row  = idx / (17 * 64);
    int t    = row & (SEQ - 1);
    int off  = (head < 16) ? head * HD : 2048;
    const float* p = qkv + (size_t)row * QKV_COLS + off;
    float freq = expf(-(4.0f * (float)i + 1.0f) * (9.210340371976184f / 128.0f));
    float ang = (float)t * freq;
    float c = cosf(ang), s = sinf(ang);
    float x1 = p[i], x2 = p[i + 64];
    float y1 = x1 * c - x2 * s;
    float y2 = x2 * c + x1 * s;
    __nv_bfloat16 h1 = __float2bfloat16(y1), h2 = __float2bfloat16(y2);
    if (head < 16) {
        size_t o = (size_t)row * NEMB + head * HD;
        qh[o + i]      = h1;  ql[o + i]      = __float2bfloat16(y1 - __bfloat162float(h1));
        qh[o + i + 64] = h2;  ql[o + i + 64] = __float2bfloat16(y2 - __bfloat162float(h2));
    } else {
        size_t o = (size_t)row * HD;
        kh[o + i]      = h1;  kl[o + i]      = __float2bfloat16(y1 - __bfloat162float(h1));
        kh[o + i + 64] = h2;  kl[o + i + 64] = __float2bfloat16(y2 - __bfloat162float(h2));
    }
}

// ---------------------------------------------------------------------------
// V transpose + split: qkv[b*SEQ+t][2176+d] -> vt[b][d][t] bf16 hi/lo
// ---------------------------------------------------------------------------
__global__ void vt_split_kernel(const float* __restrict__ qkv,
                                __nv_bfloat16* __restrict__ vth,
                                __nv_bfloat16* __restrict__ vtl) {
    __shared__ float tile[32][33];
    int t0 = blockIdx.x * 32, d0 = blockIdx.y * 32, b = blockIdx.z;
    int tx = threadIdx.x, ty = threadIdx.y;
    #pragma unroll
    for (int r = ty; r < 32; r += 8)
        tile[r][tx] = qkv[(size_t)(b * SEQ + t0 + r) * QKV_COLS + 2176 + d0 + tx];
    __syncthreads();
    #pragma unroll
    for (int r = ty; r < 32; r += 8) {
        float v = tile[tx][r];
        __nv_bfloat16 h = __float2bfloat16(v);
        size_t o = ((size_t)b * HD + d0 + r) * SEQ + t0 + tx;
        vth[o] = h;
        vtl[o] = __float2bfloat16(v - __bfloat162float(h));
    }
}

// ---------------------------------------------------------------------------
extern "C" void kernel_launch(void* const* d_in, const int* in_sizes, int n_in,
                              void* d_out, int out_size) {
    const float* x      = (const float*)d_in[0];
    const float* w_attn = (const float*)d_in[1];
    const float* w_out  = (const float*)d_in[2];
    float* out = (float*)d_out;

    float *qkv;
    __nv_bfloat16 *xhi, *xlo, *wath, *watl, *woth, *wotl, *atth, *attl;
    __nv_bfloat16 *qhi, *qlo, *khi, *klo, *vth, *vtl;
    cudaGetSymbolAddress((void**)&qkv,  g_qkv);
    cudaGetSymbolAddress((void**)&xhi,  g_x_hi);
    cudaGetSymbolAddress((void**)&xlo,  g_x_lo);
    cudaGetSymbolAddress((void**)&wath, g_wat_hi);
    cudaGetSymbolAddress((void**)&watl, g_wat_lo);
    cudaGetSymbolAddress((void**)&woth, g_wot_hi);
    cudaGetSymbolAddress((void**)&wotl, g_wot_lo);
    cudaGetSymbolAddress((void**)&atth, g_att_hi);
    cudaGetSymbolAddress((void**)&attl, g_att_lo);
    cudaGetSymbolAddress((void**)&qhi,  g_q_hi);
    cudaGetSymbolAddress((void**)&qlo,  g_q_lo);
    cudaGetSymbolAddress((void**)&khi,  g_k_hi);
    cudaGetSymbolAddress((void**)&klo,  g_k_lo);
    cudaGetSymbolAddress((void**)&vth,  g_vt_hi);
    cudaGetSymbolAddress((void**)&vtl,  g_vt_lo);

    cudaFuncSetAttribute(hmma_gemm_kernel, cudaFuncAttributeMaxDynamicSharedMemorySize, GEMM_SMEM);
    cudaFuncSetAttribute(hmma_attn_kernel, cudaFuncAttributeMaxDynamicSharedMemorySize, ATT_SMEM);

    // 0) precision splits
    int nx = ROWS * NEMB;
    split_kernel<<<nx / (4 * 256), 256>>>(x, xhi, xlo, nx);
    transpose_split_kernel<<<dim3(QKV_COLS / 32, NEMB / 32), dim3(32, 8)>>>(w_attn, wath, watl, NEMB, QKV_COLS);
    transpose_split_kernel<<<dim3(NEMB / 32, NEMB / 32), dim3(32, 8)>>>(w_out, woth, wotl, NEMB, NEMB);

    // 1) qkv = x @ w_attn  (HMMA split-bf16)
    hmma_gemm_kernel<<<dim3(QKV_COLS / 128, ROWS / 128), 256, GEMM_SMEM>>>(
        xhi, xlo, wath, watl, qkv, ROWS, QKV_COLS, NEMB);

    // 2) RoPE + split q,k ; transpose + split v
    int rope_total = ROWS * 17 * 64;
    rope_split_kernel<<<(rope_total + 255) / 256, 256>>>(qkv, qhi, qlo, khi, klo);
    vt_split_kernel<<<dim3(SEQ / 32, HD / 32, BATCH), dim3(32, 8)>>>(qkv, vth, vtl);

    // 3) HMMA flash attention -> att hi/lo
    hmma_attn_kernel<<<dim3(SEQ / 128, NHEAD, BATCH), 256, ATT_SMEM>>>(
        qhi, qlo, khi, klo, vth, vtl, atth, attl);

    // 4) out = att @ w_out  (HMMA split-bf16)
    hmma_gemm_kernel<<<dim3(NEMB / 128, ROWS / 128), 256, GEMM_SMEM>>>(
        atth, attl, woth, wotl, out, ROWS, NEMB, NEMB);
}

// round 13
// speedup vs baseline: 1.1186x; 1.0089x over previous
#include <cuda_runtime.h>
#include <cuda_bf16.h>
#include <cstdint>
#include <math.h>

#define BATCH   2
#define SEQ     2048
#define NEMB    2048
#define NHEAD   16
#define HD      128
#define QKV_COLS 2304          // (16+2)*128
#define ROWS    (BATCH*SEQ)    // 4096

// ---------------- scratch (no cudaMalloc allowed) ----------------
__device__ float g_qkv[ROWS * QKV_COLS];
__device__ __nv_bfloat16 g_x_hi[ROWS * NEMB];
__device__ __nv_bfloat16 g_x_lo[ROWS * NEMB];
__device__ __nv_bfloat16 g_wat_hi[QKV_COLS * NEMB];   // transposed [N][K]
__device__ __nv_bfloat16 g_wat_lo[QKV_COLS * NEMB];
__device__ __nv_bfloat16 g_wot_hi[NEMB * NEMB];       // transposed [N][K]
__device__ __nv_bfloat16 g_wot_lo[NEMB * NEMB];
__device__ __nv_bfloat16 g_att_hi[ROWS * NEMB];
__device__ __nv_bfloat16 g_att_lo[ROWS * NEMB];
__device__ __nv_bfloat16 g_q_hi[ROWS * NEMB];         // post-RoPE q
__device__ __nv_bfloat16 g_q_lo[ROWS * NEMB];
__device__ __nv_bfloat16 g_k_hi[ROWS * HD];           // post-RoPE k [b*SEQ+t][128]
__device__ __nv_bfloat16 g_k_lo[ROWS * HD];
__device__ __nv_bfloat16 g_vt_hi[BATCH * HD * SEQ];   // v transposed [b][d][t]
__device__ __nv_bfloat16 g_vt_lo[BATCH * HD * SEQ];

// ---------------- PTX helpers (baseline ISA only: sm_80-class) ----------------
__device__ __forceinline__ uint32_t smem_u32(const void* p) {
    uint32_t a;
    asm("{ .reg .u64 t; cvta.to.shared.u64 t, %1; cvt.u32.u64 %0, t; }" : "=r"(a) : "l"(p));
    return a;
}
#define CP_ASYNC16(s, g) \
    asm volatile("cp.async.cg.shared.global [%0], [%1], 16;" :: "r"(s), "l"(g) : "memory")
#define CP_COMMIT() asm volatile("cp.async.commit_group;" ::: "memory")
#define CP_WAIT1()  asm volatile("cp.async.wait_group 1;" ::: "memory")
#define CP_WAIT0()  asm volatile("cp.async.wait_group 0;" ::: "memory")
#define LDSM_X4(r, a) \
    asm volatile("ldmatrix.sync.aligned.m8n8.x4.shared.b16 {%0,%1,%2,%3}, [%4];" \
        : "=r"((r)[0]), "=r"((r)[1]), "=r"((r)[2]), "=r"((r)[3]) : "r"(a))

__device__ __forceinline__ void mma_bf16(float* d, const uint32_t* a, uint32_t b0, uint32_t b1) {
    asm volatile(
        "mma.sync.aligned.m16n8k16.row.col.f32.bf16.bf16.f32 "
        "{%0,%1,%2,%3}, {%4,%5,%6,%7}, {%8,%9}, {%0,%1,%2,%3};"
        : "+f"(d[0]), "+f"(d[1]), "+f"(d[2]), "+f"(d[3])
        : "r"(a[0]), "r"(a[1]), "r"(a[2]), "r"(a[3]), "r"(b0), "r"(b1));
}
__device__ __forceinline__ uint32_t pack_bf16(float x, float y) {
    __nv_bfloat162 t = __floats2bfloat162_rn(x, y);
    return *(uint32_t*)&t;
}

// ---------------------------------------------------------------------------
// HMMA split-bf16 GEMM: C[M,N] fp32 = (Ah+Al)[M,K] @ (Bh+Bl)[N,K]^T
// 128x128 CTA tile, k-chunk 32, 3-stage cp.async, ONE sync per chunk,
// XOR-swizzled 64B rows (no padding) so 3 stages fit in 96KB -> 2 CTAs/SM.
// Swizzle: phys_col16 = col16 ^ ((row>>1)&3). Store & load use same formula.
// ---------------------------------------------------------------------------
#define GBUF_B   8192                  // 128 rows x 64B, one logical tile
#define GSTAGE_B (4 * GBUF_B)          // Ah, Al, Bh, Bl = 32768
#define GEMM_SMEM (3 * GSTAGE_B)       // 98304 -> 2 CTAs/SM

__global__ __launch_bounds__(256, 2) void hmma_gemm_kernel(
    const __nv_bfloat16* __restrict__ Ah, const __nv_bfloat16* __restrict__ Al,
    const __nv_bfloat16* __restrict__ Bh, const __nv_bfloat16* __restrict__ Bl,
    float* __restrict__ C, int M, int N, int K)
{
    extern __shared__ char smem[];
    const uint32_t sb = smem_u32(smem);
    const int tid  = threadIdx.x;
    const int lane = tid & 31;
    const int warp = tid >> 5;
    const int m0 = blockIdx.y * 128, n0 = blockIdx.x * 128;
    const int wm = (warp >> 2) * 64, wn = (warp & 3) * 32;

    const int crow = tid >> 1;
    const int ccol = (tid & 1) * 2;
    const int csw  = (crow >> 1) & 3;
    const uint32_t cd0 = crow * 64 + ((ccol    ) ^ csw) * 16;
    const uint32_t cd1 = crow * 64 + ((ccol + 1) ^ csw) * 16;
    const char* gsrc[4];
    gsrc[0] = (const char*)(Ah + (size_t)(m0 + crow) * K);
    gsrc[1] = (const char*)(Al + (size_t)(m0 + crow) * K);
    gsrc[2] = (const char*)(Bh + (size_t)(n0 + crow) * K);
    gsrc[3] = (const char*)(Bl + (size_t)(n0 + crow) * K);

    const int nch = K / 32;
    float acc[4][4][4] = {};
    const int lr = lane & 15;
    const int lc = lane >> 4;

    auto issue = [&](int ch, int st) {
        const uint32_t so = sb + st * GSTAGE_B;
        #pragma unroll
        for (int b = 0; b < 4; b++) {
            const char* g = gsrc[b] + (size_t)ch * 64 + ccol * 16;
            uint32_t s0 = so + b * GBUF_B;
            CP_ASYNC16(s0 + cd0, g);
            CP_ASYNC16(s0 + cd1, g + 16);
        }
        CP_COMMIT();
    };

    uint32_t arow[4], asw[4], brow[2], bsw[2];
    #pragma unroll
    for (int ma = 0; ma < 4; ma++) {
        int r = wm + ma * 16 + lr;
        arow[ma] = r * 64; asw[ma] = (r >> 1) & 3;
    }
    #pragma unroll
    for (int ng = 0; ng < 2; ng++) {
        int r = wn + ng * 16 + lr;
        brow[ng] = r * 64; bsw[ng] = (r >> 1) & 3;
    }

    issue(0, 0);
    issue(1, 1);
    int stg = 0;
    for (int ch = 0; ch < nch; ch++) {
        if (ch == nch - 1) { CP_WAIT0(); } else { CP_WAIT1(); }
        __syncthreads();
        if (ch + 2 < nch) issue(ch + 2, stg == 0 ? 2 : stg - 1);

        const uint32_t stage = sb + stg * GSTAGE_B;

        #pragma unroll
        for (int kh = 0; kh < 2; kh++) {
            const uint32_t col = kh * 2 + lc;
            uint32_t ah[4][4], al[4][4], bh[2][4], bl[2][4];
            #pragma unroll
            for (int ma = 0; ma < 4; ma++) {
                uint32_t ad = stage + arow[ma] + ((col ^ asw[ma]) << 4);
                LDSM_X4(ah[ma], ad);
                LDSM_X4(al[ma], ad + GBUF_B);
            }
            #pragma unroll
            for (int ng = 0; ng < 2; ng++) {
                uint32_t bd = stage + 2 * GBUF_B + brow[ng] + ((col ^ bsw[ng]) << 4);
                LDSM_X4(bh[ng], bd);
                LDSM_X4(bl[ng], bd + GBUF_B);
            }
            #pragma unroll
            for (int ma = 0; ma < 4; ma++)
                #pragma unroll
                for (int na = 0; na < 4; na++) {
                    const int ng = na >> 1, hi = na & 1;
                    mma_bf16(acc[ma][na], ah[ma], bh[ng][hi], bh[ng][hi + 2]);
                    mma_bf16(acc[ma][na], ah[ma], bl[ng][hi], bl[ng][hi + 2]);
                    mma_bf16(acc[ma][na], al[ma], bh[ng][hi], bh[ng][hi + 2]);
                }
        }
        stg = (stg == 2) ? 0 : stg + 1;
    }

    const int gr = lane >> 2, gc = (lane & 3) * 2;
    #pragma unroll
    for (int ma = 0; ma < 4; ma++) {
        #pragma unroll
        for (int na = 0; na < 4; na++) {
            size_t r = (size_t)(m0 + wm + ma * 16 + gr);
            size_t c = (size_t)(n0 + wn + na * 8 + gc);
            *(float2*)&C[r * N + c]       = make_float2(acc[ma][na][0], acc[ma][na][1]);
            *(float2*)&C[(r + 8) * N + c] = make_float2(acc[ma][na][2], acc[ma][na][3]);
        }
    }
}

// ---------------------------------------------------------------------------
// HMMA flash attention (no-max softmax), split-bf16, kv-tile 64 (32 iters),
// 2-stage K/V pipeline. Block = (128 q rows, head, batch),
// 8 warps x (16 q rows x 64 keys).
// ---------------------------------------------------------------------------
#define BKT  64
#define QSTR 272
#define KSTR 272
#define VSTR 144
#define SM_QB  (128*QSTR)           // 34816 per Q split
#define SM_K   (2*SM_QB)            // 69632
#define KBUF   (BKT*KSTR)           // 17408
#define KSTAGE (2*KBUF)             // 34816
#define SM_V   (SM_K + 2*KSTAGE)    // 139264
#define VBUF   (128*VSTR)           // 18432
#define VSTAGE (2*VBUF)             // 36864
#define ATT_SMEM (SM_V + 2*VSTAGE)  // 212992

__global__ __launch_bounds__(256, 1) void hmma_attn_kernel(
    const __nv_bfloat16* __restrict__ qh_g, const __nv_bfloat16* __restrict__ ql_g,
    const __nv_bfloat16* __restrict__ kh_g, const __nv_bfloat16* __restrict__ kl_g,
    const __nv_bfloat16* __restrict__ vth_g, const __nv_bfloat16* __restrict__ vtl_g,
    __nv_bfloat16* __restrict__ oh_g, __nv_bfloat16* __restrict__ ol_g)
{
    extern __shared__ char smem[];
    const uint32_t sb = smem_u32(smem);
    const int qt = blockIdx.x, h = blockIdx.y, b = blockIdx.z;
    const int tid = threadIdx.x, lane = tid & 31, warp = tid >> 5;
    const int lr = lane & 15, lc = lane >> 4;
    const int gr = lane >> 2, gc = (lane & 3) * 2;

    // Q tile cp.async (both splits), folded into group 0
    {
        const char* s0 = (const char*)(qh_g + (size_t)(b * SEQ + qt * 128) * NEMB + h * 128);
        const char* s1 = (const char*)(ql_g + (size_t)(b * SEQ + qt * 128) * NEMB + h * 128);
        #pragma unroll
        for (int i = 0; i < 8; i++) {
            int c = tid + i * 256;
            int row = c >> 4, off = (c & 15) * 16;
            CP_ASYNC16(sb + row * QSTR + off,         s0 + (size_t)row * (NEMB * 2) + off);
            CP_ASYNC16(sb + SM_QB + row * QSTR + off, s1 + (size_t)row * (NEMB * 2) + off);
        }
    }
    auto issue = [&](int kt) {
        uint32_t kb = sb + SM_K + (kt & 1) * KSTAGE;
        uint32_t vb = sb + SM_V + (kt & 1) * VSTAGE;
        const char* ksh = (const char*)(kh_g + (size_t)(b * SEQ + kt * BKT) * HD);
        const char* ksl = (const char*)(kl_g + (size_t)(b * SEQ + kt * BKT) * HD);
        #pragma unroll
        for (int i = 0; i < 4; i++) {
            int c = tid + i * 256;
            int row = c >> 4, off = (c & 15) * 16;
            CP_ASYNC16(kb + row * KSTR + off,        ksh + (size_t)row * 256 + off);
            CP_ASYNC16(kb + KBUF + row * KSTR + off, ksl + (size_t)row * 256 + off);
        }
        const char* vsh = (const char*)(vth_g + (size_t)b * HD * SEQ + kt * (BKT * 2) / 2);
        const char* vsl = (const char*)(vtl_g + (size_t)b * HD * SEQ + kt * (BKT * 2) / 2);
        #pragma unroll
        for (int i = 0; i < 4; i++) {
            int c = tid + i * 256;
            int row = c >> 3, off = (c & 7) * 16;
            CP_ASYNC16(vb + row * VSTR + off,        vsh + (size_t)row * (SEQ * 2) + off);
            CP_ASYNC16(vb + VBUF + row * VSTR + off, vsl + (size_t)row * (SEQ * 2) + off);
        }
    };
    issue(0); CP_COMMIT();
    issue(1); CP_COMMIT();

    float oacc[16][4] = {};
    float lsum0 = 0.f, lsum1 = 0.f;
    const float SC2 = 0.08838834764831845f * 1.44269504088896f;  // scale * log2(e)

    const uint32_t qah = sb + (warp * 16 + lr) * QSTR + lc * 16;
    const uint32_t qal = qah + SM_QB;

    const int NKT = SEQ / BKT;      // 32
    for (int kt = 0; kt < NKT; kt++) {
        if (kt == NKT - 1) { CP_WAIT0(); } else { CP_WAIT1(); }
        __syncthreads();
        const uint32_t kb = sb + SM_K + (kt & 1) * KSTAGE;
        const uint32_t vb = sb + SM_V + (kt & 1) * VSTAGE;

        // ---- S = Q @ K^T over 64 keys (split: hh + hl + lh) ----
        float sacc[8][4] = {};
        #pragma unroll
        for (int kh = 0; kh < 8; kh++) {
            uint32_t qfh[4], qfl[4], kfh[4][4], kfl[4][4];
            LDSM_X4(qfh, qah + kh * 32);
            LDSM_X4(qfl, qal + kh * 32);
            #pragma unroll
            for (int g = 0; g < 4; g++) {
                uint32_t ka = kb + (g * 16 + lr) * KSTR + kh * 32 + lc * 16;
                LDSM_X4(kfh[g], ka);
                LDSM_X4(kfl[g], ka + KBUF);
            }
            #pragma unroll
            for (int na = 0; na < 8; na++) {
                const int g = na >> 1, hi = na & 1;
                mma_bf16(sacc[na], qfh, kfh[g][hi], kfh[g][hi + 2]);
                mma_bf16(sacc[na], qfh, kfl[g][hi], kfl[g][hi + 2]);
                mma_bf16(sacc[na], qfl, kfh[g][hi], kfh[g][hi + 2]);
            }
        }

        // ---- P = exp(S*scale); accumulate row sums; build split A-frags ----
        uint32_t pah[4][4], pal[4][4];
        float l0 = 0.f, l1 = 0.f;
        #pragma unroll
        for (int na = 0; na < 8; na++) {
            float p0 = exp2f(sacc[na][0] * SC2);
            float p1 = exp2f(sacc[na][1] * SC2);
            float p2 = exp2f(sacc[na][2] * SC2);
            float p3 = exp2f(sacc[na][3] * SC2);
            l0 += p0 + p1; l1 += p2 + p3;
            const int t = na >> 1, half = na & 1;
            __nv_bfloat16 h0 = __float2bfloat16(p0), h1 = __float2bfloat16(p1);
            __nv_bfloat16 h2 = __float2bfloat16(p2), h3 = __float2bfloat16(p3);
            pah[t][half * 2 + 0] = pack_bf16(__bfloat162float(h0), __bfloat162float(h1));
            pah[t][half * 2 + 1] = pack_bf16(__bfloat162float(h2), __bfloat162float(h3));
            pal[t][half * 2 + 0] = pack_bf16(p0 - __bfloat162float(h0), p1 - __bfloat162float(h1));
            pal[t][half * 2 + 1] = pack_bf16(p2 - __bfloat162float(h2), p3 - __bfloat162float(h3));
        }
        l0 += __shfl_xor_sync(0xffffffffu, l0, 1);
        l0 += __shfl_xor_sync(0xffffffffu, l0, 2);
        l1 += __shfl_xor_sync(0xffffffffu, l1, 1);
        l1 += __shfl_xor_sync(0xffffffffu, l1, 2);
        lsum0 += l0; lsum1 += l1;

        // ---- O += P @ V (split: hh + hl + lh) ----
        #pragma unroll
        for (int nb8 = 0; nb8 < 8; nb8++) {
            uint32_t vfh[4][4], vfl[4][4];
            #pragma unroll
            for (int ka = 0; ka < 4; ka++) {
                uint32_t va = vb + (nb8 * 16 + lr) * VSTR + ka * 32 + lc * 16;
                LDSM_X4(vfh[ka], va);
                LDSM_X4(vfl[ka], va + VBUF);
            }
            #pragma unroll
            for (int ns = 0; ns < 2; ns++) {
                const int n = nb8 * 2 + ns;
                #pragma unroll
                for (int t = 0; t < 4; t++) {
                    mma_bf16(oacc[n], pah[t], vfh[t][ns], vfh[t][ns + 2]);
                    mma_bf16(oacc[n], pah[t], vfl[t][ns], vfl[t][ns + 2]);
                    mma_bf16(oacc[n], pal[t], vfh[t][ns], vfh[t][ns + 2]);
                }
            }
        }
        __syncthreads();
        if (kt + 2 < NKT) { issue(kt + 2); CP_COMMIT(); }
    }

    // ---- epilogue: normalize, split to bf16 hi/lo ----
    const float inv0 = 1.f / lsum0, inv1 = 1.f / lsum1;
    const size_t row0 = (size_t)(b * SEQ + qt * 128 + warp * 16 + gr);
    #pragma unroll
    for (int n = 0; n < 16; n++) {
        const size_t col = (size_t)h * 128 + n * 8 + gc;
        float v0 = oacc[n][0] * inv0, v1 = oacc[n][1] * inv0;
        float v2 = oacc[n][2] * inv1, v3 = oacc[n][3] * inv1;
        __nv_bfloat16 h0 = __float2bfloat16(v0), h1 = __float2bfloat16(v1);
        __nv_bfloat16 h2 = __float2bfloat16(v2), h3 = __float2bfloat16(v3);
        *(uint32_t*)&oh_g[row0 * NEMB + col] = pack_bf16(__bfloat162float(h0), __bfloat162float(h1));
        *(uint32_t*)&ol_g[row0 * NEMB + col] = pack_bf16(v0 - __bfloat162float(h0), v1 - __bfloat162float(h1));
        *(uint32_t*)&oh_g[(row0 + 8) * NEMB + col] = pack_bf16(__bfloat162float(h2), __bfloat162float(h3));
        *(uint32_t*)&ol_g[(row0 + 8) * NEMB + col] = pack_bf16(v2 - __bfloat162float(h2), v3 - __bfloat162float(h3));
    }
}

// ---------------------------------------------------------------------------
// fp32 -> bf16 hi/lo split
// ---------------------------------------------------------------------------
__global__ void split_kernel(const float* __restrict__ in,
                             __nv_bfloat16* __restrict__ hi,
                             __nv_bfloat16* __restrict__ lo, int n) {
    int i = (blockIdx.x * blockDim.x + threadIdx.x) * 4;
    if (i >= n) return;
    float4 v = *(const float4*)(in + i);
    __nv_bfloat16 h0 = __float2bfloat16(v.x), h1 = __float2bfloat16(v.y);
    __nv_bfloat16 h2 = __float2bfloat16(v.z), h3 = __float2bfloat16(v.w);
    __nv_bfloat162* H = (__nv_bfloat162*)(hi + i);
    __nv_bfloat162* L = (__nv_bfloat162*)(lo + i);
    H[0] = __nv_bfloat162(h0, h1); H[1] = __nv_bfloat162(h2, h3);
    L[0] = __nv_bfloat162(__float2bfloat16(v.x - __bfloat162float(h0)),
                          __float2bfloat16(v.y - __bfloat162float(h1)));
    L[1] = __nv_bfloat162(__float2bfloat16(v.z - __bfloat162float(h2)),
                          __float2bfloat16(v.w - __bfloat162float(h3)));
}

// ---------------------------------------------------------------------------
// transpose + split: w[K][N] fp32 -> hi/lo[N][K] bf16
// ---------------------------------------------------------------------------
__global__ void transpose_split_kernel(const float* __restrict__ w,
                                       __nv_bfloat16* __restrict__ hi,
                                       __nv_bfloat16* __restrict__ lo,
                                       int K, int N) {
    __shared__ float t[32][33];
    int n0 = blockIdx.x * 32, k0 = blockIdx.y * 32;
    int tx = threadIdx.x, ty = threadIdx.y;
    #pragma unroll
    for (int r = ty; r < 32; r += 8)
        t[r][tx] = w[(size_t)(k0 + r) * N + n0 + tx];
    __syncthreads();
    #pragma unroll
    for (int r = ty; r < 32; r += 8) {
        float v = t[tx][r];
        __nv_bfloat16 h = __float2bfloat16(v);
        size_t o = (size_t)(n0 + r) * K + k0 + tx;
        hi[o] = h;
        lo[o] = __float2bfloat16(v - __bfloat162float(h));
    }
}

// ---------------------------------------------------------------------------
// RoPE + split q,k -> bf16 hi/lo
// ---------------------------------------------------------------------------
__global__ void rope_split_kernel(const float* __restrict__ qkv,
                                  __nv_bfloat16* __restrict__ qh, __nv_bfloat16* __restrict__ ql,
                                  __nv_bfloat16* __restrict__ kh, __nv_bfloat16* __restrict__ kl) {
    const int total = ROWS * 17 * 64;
    int idx = blockIdx.x * blockDim.x + threadIdx.x;
    if (idx >= total) return;
    int i    = idx & 63;
    int head = (idx >> 6) % 17;
    int row  = idx / (17 * 64);
    int t    = row & (SEQ - 1);
    int off  = (head < 16) ? head * HD : 2048;
    const float* p = qkv + (size_t)row * QKV_COLS + off;
    float freq = expf(-(4.0f * (float)i + 1.0f) * (9.210340371976184f / 128.0f));
    float ang = (float)t * freq;
    float c = cosf(ang), s = sinf(ang);
    float x1 = p[i], x2 = p[i + 64];
    float y1 = x1 * c - x2 * s;
    float y2 = x2 * c + x1 * s;
    __nv_bfloat16 h1 = __float2bfloat16(y1), h2 = __float2bfloat16(y2);
    if (head < 16) {
        size_t o = (size_t)row * NEMB + head * HD;
        qh[o + i]      = h1;  ql[o + i]      = __float2bfloat16(y1 - __bfloat162float(h1));
        qh[o + i + 64] = h2;  ql[o + i + 64] = __float2bfloat16(y2 - __bfloat162float(h2));
    } else {
        size_t o = (size_t)row * HD;
        kh[o + i]      = h1;  kl[o + i]      = __float2bfloat16(y1 - __bfloat162float(h1));
        kh[o + i + 64] = h2;  kl[o + i + 64] = __float2bfloat16(y2 - __bfloat162float(h2));
    }
}

// ---------------------------------------------------------------------------
// V transpose + split: qkv[b*SEQ+t][2176+d] -> vt[b][d][t] bf16 hi/lo
// ---------------------------------------------------------------------------
__global__ void vt_split_kernel(const float* __restrict__ qkv,
                                __nv_bfloat16* __restrict__ vth,
                                __nv_bfloat16* __restrict__ vtl) {
    __shared__ float tile[32][33];
    int t0 = blockIdx.x * 32, d0 = blockIdx.y * 32, b = blockIdx.z;
    int tx = threadIdx.x, ty = threadIdx.y;
    #pragma unroll
    for (int r = ty; r < 32; r += 8)
        tile[r][tx] = qkv[(size_t)(b * SEQ + t0 + r) * QKV_COLS + 2176 + d0 + tx];
    __syncthreads();
    #pragma unroll
    for (int r = ty; r < 32; r += 8) {
        float v = tile[tx][r];
        __nv_bfloat16 h = __float2bfloat16(v);
        size_t o = ((size_t)b * HD + d0 + r) * SEQ + t0 + tx;
        vth[o] = h;
        vtl[o] = __float2bfloat16(v - __bfloat162float(h));
    }
}

// ---------------------------------------------------------------------------
extern "C" void kernel_launch(void* const* d_in, const int* in_sizes, int n_in,
                              void* d_out, int out_size) {
    const float* x      = (const float*)d_in[0];
    const float* w_attn = (const float*)d_in[1];
    const float* w_out  = (const float*)d_in[2];
    float* out = (float*)d_out;

    float *qkv;
    __nv_bfloat16 *xhi, *xlo, *wath, *watl, *woth, *wotl, *atth, *attl;
    __nv_bfloat16 *qhi, *qlo, *khi, *klo, *vth, *vtl;
    cudaGetSymbolAddress((void**)&qkv,  g_qkv);
    cudaGetSymbolAddress((void**)&xhi,  g_x_hi);
    cudaGetSymbolAddress((void**)&xlo,  g_x_lo);
    cudaGetSymbolAddress((void**)&wath, g_wat_hi);
    cudaGetSymbolAddress((void**)&watl, g_wat_lo);
    cudaGetSymbolAddress((void**)&woth, g_wot_hi);
    cudaGetSymbolAddress((void**)&wotl, g_wot_lo);
    cudaGetSymbolAddress((void**)&atth, g_att_hi);
    cudaGetSymbolAddress((void**)&attl, g_att_lo);
    cudaGetSymbolAddress((void**)&qhi,  g_q_hi);
    cudaGetSymbolAddress((void**)&qlo,  g_q_lo);
    cudaGetSymbolAddress((void**)&khi,  g_k_hi);
    cudaGetSymbolAddress((void**)&klo,  g_k_lo);
    cudaGetSymbolAddress((void**)&vth,  g_vt_hi);
    cudaGetSymbolAddress((void**)&vtl,  g_vt_lo);

    cudaFuncSetAttribute(hmma_gemm_kernel, cudaFuncAttributeMaxDynamicSharedMemorySize, GEMM_SMEM);
    cudaFuncSetAttribute(hmma_attn_kernel, cudaFuncAttributeMaxDynamicSharedMemorySize, ATT_SMEM);

    // 0) precision splits
    int nx = ROWS * NEMB;
    split_kernel<<<nx / (4 * 256), 256>>>(x, xhi, xlo, nx);
    transpose_split_kernel<<<dim3(QKV_COLS / 32, NEMB / 32), dim3(32, 8)>>>(w_attn, wath, watl, NEMB, QKV_COLS);
    transpose_split_kernel<<<dim3(NEMB / 32, NEMB / 32), dim3(32, 8)>>>(w_out, woth, wotl, NEMB, NEMB);

    // 1) qkv = x @ w_attn  (HMMA split-bf16)
    hmma_gemm_kernel<<<dim3(QKV_COLS / 128, ROWS / 128), 256, GEMM_SMEM>>>(
        xhi, xlo, wath, watl, qkv, ROWS, QKV_COLS, NEMB);

    // 2) RoPE + split q,k ; transpose + split v
    int rope_total = ROWS * 17 * 64;
    rope_split_kernel<<<(rope_total + 255) / 256, 256>>>(qkv, qhi, qlo, khi, klo);
    vt_split_kernel<<<dim3(SEQ / 32, HD / 32, BATCH), dim3(32, 8)>>>(qkv, vth, vtl);

    // 3) HMMA flash attention -> att hi/lo
    hmma_attn_kernel<<<dim3(SEQ / 128, NHEAD, BATCH), 256, ATT_SMEM>>>(
        qhi, qlo, khi, klo, vth, vtl, atth, attl);

    // 4) out = att @ w_out  (HMMA split-bf16)
    hmma_gemm_kernel<<<dim3(NEMB / 128, ROWS / 128), 256, GEMM_SMEM>>>(
        atth, attl, woth, wotl, out, ROWS, NEMB, NEMB);
}

// round 16
// speedup vs baseline: 1.6164x; 1.4449x over previous
#include <cuda_runtime.h>
#include <cuda_bf16.h>
#include <cuda_fp16.h>
#include <cstdint>
#include <math.h>

#define BATCH   2
#define SEQ     2048
#define NEMB    2048
#define NHEAD   16
#define HD      128
#define QKV_COLS 2304          // (16+2)*128
#define ROWS    (BATCH*SEQ)    // 4096

// ---------------- scratch (no cudaMalloc allowed) ----------------
__device__ float g_qkv[ROWS * QKV_COLS];
__device__ __nv_bfloat16 g_x_hi[ROWS * NEMB];
__device__ __nv_bfloat16 g_x_lo[ROWS * NEMB];
__device__ __nv_bfloat16 g_wat_hi[QKV_COLS * NEMB];   // transposed [N][K]
__device__ __nv_bfloat16 g_wat_lo[QKV_COLS * NEMB];
__device__ __half        g_wot_h[NEMB * NEMB];        // transposed [N][K], fp16
__device__ __half        g_att_h[ROWS * NEMB];        // attention out, fp16
__device__ __nv_bfloat16 g_q_hi[ROWS * NEMB];         // post-RoPE q
__device__ __nv_bfloat16 g_q_lo[ROWS * NEMB];
__device__ __nv_bfloat16 g_k_hi[ROWS * HD];           // post-RoPE k
__device__ __nv_bfloat16 g_k_lo[ROWS * HD];
__device__ __half        g_vt_h[BATCH * HD * SEQ];    // v transposed [b][d][t], fp16

// ---------------- PTX helpers (baseline ISA only: sm_80-class) ----------------
__device__ __forceinline__ uint32_t smem_u32(const void* p) {
    uint32_t a;
    asm("{ .reg .u64 t; cvta.to.shared.u64 t, %1; cvt.u32.u64 %0, t; }" : "=r"(a) : "l"(p));
    return a;
}
#define CP_ASYNC16(s, g) \
    asm volatile("cp.async.cg.shared.global [%0], [%1], 16;" :: "r"(s), "l"(g) : "memory")
#define CP_COMMIT() asm volatile("cp.async.commit_group;" ::: "memory")
#define CP_WAIT1()  asm volatile("cp.async.wait_group 1;" ::: "memory")
#define CP_WAIT0()  asm volatile("cp.async.wait_group 0;" ::: "memory")
#define LDSM_X4(r, a) \
    asm volatile("ldmatrix.sync.aligned.m8n8.x4.shared.b16 {%0,%1,%2,%3}, [%4];" \
        : "=r"((r)[0]), "=r"((r)[1]), "=r"((r)[2]), "=r"((r)[3]) : "r"(a))

__device__ __forceinline__ void mma_bf16(float* d, const uint32_t* a, uint32_t b0, uint32_t b1) {
    asm volatile(
        "mma.sync.aligned.m16n8k16.row.col.f32.bf16.bf16.f32 "
        "{%0,%1,%2,%3}, {%4,%5,%6,%7}, {%8,%9}, {%0,%1,%2,%3};"
        : "+f"(d[0]), "+f"(d[1]), "+f"(d[2]), "+f"(d[3])
        : "r"(a[0]), "r"(a[1]), "r"(a[2]), "r"(a[3]), "r"(b0), "r"(b1));
}
__device__ __forceinline__ void mma_f16(float* d, const uint32_t* a, uint32_t b0, uint32_t b1) {
    asm volatile(
        "mma.sync.aligned.m16n8k16.row.col.f32.f16.f16.f32 "
        "{%0,%1,%2,%3}, {%4,%5,%6,%7}, {%8,%9}, {%0,%1,%2,%3};"
        : "+f"(d[0]), "+f"(d[1]), "+f"(d[2]), "+f"(d[3])
        : "r"(a[0]), "r"(a[1]), "r"(a[2]), "r"(a[3]), "r"(b0), "r"(b1));
}
__device__ __forceinline__ uint32_t pack_bf16(float x, float y) {
    __nv_bfloat162 t = __floats2bfloat162_rn(x, y);
    return *(uint32_t*)&t;
}
__device__ __forceinline__ uint32_t pack_f16(float x, float y) {
    __half2 t = __floats2half2_rn(x, y);
    return *(uint32_t*)&t;
}

// ---------------------------------------------------------------------------
// HMMA split-bf16 GEMM (GEMM1): C[M,N] fp32 = (Ah+Al)[M,K] @ (Bh+Bl)[N,K]^T
// 128x128 tile, k-chunk 32, 3-stage, XOR-swizzled 64B rows, 2 CTAs/SM.
// ---------------------------------------------------------------------------
#define GBUF_B   8192
#define GSTAGE_B (4 * GBUF_B)          // 32768
#define GEMM_SMEM (3 * GSTAGE_B)       // 98304

__global__ __launch_bounds__(256, 2) void hmma_gemm_kernel(
    const __nv_bfloat16* __restrict__ Ah, const __nv_bfloat16* __restrict__ Al,
    const __nv_bfloat16* __restrict__ Bh, const __nv_bfloat16* __restrict__ Bl,
    float* __restrict__ C, int M, int N, int K)
{
    extern __shared__ char smem[];
    const uint32_t sb = smem_u32(smem);
    const int tid  = threadIdx.x;
    const int lane = tid & 31;
    const int warp = tid >> 5;
    const int m0 = blockIdx.y * 128, n0 = blockIdx.x * 128;
    const int wm = (warp >> 2) * 64, wn = (warp & 3) * 32;

    const int crow = tid >> 1;
    const int ccol = (tid & 1) * 2;
    const int csw  = (crow >> 1) & 3;
    const uint32_t cd0 = crow * 64 + ((ccol    ) ^ csw) * 16;
    const uint32_t cd1 = crow * 64 + ((ccol + 1) ^ csw) * 16;
    const char* gsrc[4];
    gsrc[0] = (const char*)(Ah + (size_t)(m0 + crow) * K);
    gsrc[1] = (const char*)(Al + (size_t)(m0 + crow) * K);
    gsrc[2] = (const char*)(Bh + (size_t)(n0 + crow) * K);
    gsrc[3] = (const char*)(Bl + (size_t)(n0 + crow) * K);

    const int nch = K / 32;
    float acc[4][4][4] = {};
    const int lr = lane & 15;
    const int lc = lane >> 4;

    auto issue = [&](int ch, int st) {
        const uint32_t so = sb + st * GSTAGE_B;
        #pragma unroll
        for (int b = 0; b < 4; b++) {
            const char* g = gsrc[b] + (size_t)ch * 64 + ccol * 16;
            uint32_t s0 = so + b * GBUF_B;
            CP_ASYNC16(s0 + cd0, g);
            CP_ASYNC16(s0 + cd1, g + 16);
        }
        CP_COMMIT();
    };

    uint32_t arow[4], asw[4], brow[2], bsw[2];
    #pragma unroll
    for (int ma = 0; ma < 4; ma++) {
        int r = wm + ma * 16 + lr;
        arow[ma] = r * 64; asw[ma] = (r >> 1) & 3;
    }
    #pragma unroll
    for (int ng = 0; ng < 2; ng++) {
        int r = wn + ng * 16 + lr;
        brow[ng] = r * 64; bsw[ng] = (r >> 1) & 3;
    }

    issue(0, 0);
    issue(1, 1);
    int stg = 0;
    for (int ch = 0; ch < nch; ch++) {
        if (ch == nch - 1) { CP_WAIT0(); } else { CP_WAIT1(); }
        __syncthreads();
        if (ch + 2 < nch) issue(ch + 2, stg == 0 ? 2 : stg - 1);

        const uint32_t stage = sb + stg * GSTAGE_B;

        #pragma unroll
        for (int kh = 0; kh < 2; kh++) {
            const uint32_t col = kh * 2 + lc;
            uint32_t ah[4][4], al[4][4], bh[2][4], bl[2][4];
            #pragma unroll
            for (int ma = 0; ma < 4; ma++) {
                uint32_t ad = stage + arow[ma] + ((col ^ asw[ma]) << 4);
                LDSM_X4(ah[ma], ad);
                LDSM_X4(al[ma], ad + GBUF_B);
            }
            #pragma unroll
            for (int ng = 0; ng < 2; ng++) {
                uint32_t bd = stage + 2 * GBUF_B + brow[ng] + ((col ^ bsw[ng]) << 4);
                LDSM_X4(bh[ng], bd);
                LDSM_X4(bl[ng], bd + GBUF_B);
            }
            #pragma unroll
            for (int ma = 0; ma < 4; ma++)
                #pragma unroll
                for (int na = 0; na < 4; na++) {
                    const int ng = na >> 1, hi = na & 1;
                    mma_bf16(acc[ma][na], ah[ma], bh[ng][hi], bh[ng][hi + 2]);
                    mma_bf16(acc[ma][na], ah[ma], bl[ng][hi], bl[ng][hi + 2]);
                    mma_bf16(acc[ma][na], al[ma], bh[ng][hi], bh[ng][hi + 2]);
                }
        }
        stg = (stg == 2) ? 0 : stg + 1;
    }

    const int gr = lane >> 2, gc = (lane & 3) * 2;
    #pragma unroll
    for (int ma = 0; ma < 4; ma++) {
        #pragma unroll
        for (int na = 0; na < 4; na++) {
            size_t r = (size_t)(m0 + wm + ma * 16 + gr);
            size_t c = (size_t)(n0 + wn + na * 8 + gc);
            *(float2*)&C[r * N + c]       = make_float2(acc[ma][na][0], acc[ma][na][1]);
            *(float2*)&C[(r + 8) * N + c] = make_float2(acc[ma][na][2], acc[ma][na][3]);
        }
    }
}

// ---------------------------------------------------------------------------
// HMMA single-fp16 GEMM (GEMM2): C[M,N] fp32 = A[M,K] @ B[N,K]^T, one MMA pass.
// Same swizzle/pipeline; stage = A+B tiles = 16KB; 3 stages = 48KB; 2 CTAs/SM.
// ---------------------------------------------------------------------------
#define F16_STAGE_B (2 * GBUF_B)       // 16384
#define F16_GEMM_SMEM (3 * F16_STAGE_B)  // 49152

__global__ __launch_bounds__(256, 2) void hmma_gemm_f16_kernel(
    const __half* __restrict__ A, const __half* __restrict__ B,
    float* __restrict__ C, int M, int N, int K)
{
    extern __shared__ char smem[];
    const uint32_t sb = smem_u32(smem);
    const int tid  = threadIdx.x;
    const int lane = tid & 31;
    const int warp = tid >> 5;
    const int m0 = blockIdx.y * 128, n0 = blockIdx.x * 128;
    const int wm = (warp >> 2) * 64, wn = (warp & 3) * 32;

    const int crow = tid >> 1;
    const int ccol = (tid & 1) * 2;
    const int csw  = (crow >> 1) & 3;
    const uint32_t cd0 = crow * 64 + ((ccol    ) ^ csw) * 16;
    const uint32_t cd1 = crow * 64 + ((ccol + 1) ^ csw) * 16;
    const char* gsrcA = (const char*)(A + (size_t)(m0 + crow) * K);
    const char* gsrcB = (const char*)(B + (size_t)(n0 + crow) * K);

    const int nch = K / 32;
    float acc[4][4][4] = {};
    const int lr = lane & 15;
    const int lc = lane >> 4;

    auto issue = [&](int ch, int st) {
        const uint32_t so = sb + st * F16_STAGE_B;
        const char* ga = gsrcA + (size_t)ch * 64 + ccol * 16;
        const char* gb = gsrcB + (size_t)ch * 64 + ccol * 16;
        CP_ASYNC16(so + cd0, ga);
        CP_ASYNC16(so + cd1, ga + 16);
        CP_ASYNC16(so + GBUF_B + cd0, gb);
        CP_ASYNC16(so + GBUF_B + cd1, gb + 16);
        CP_COMMIT();
    };

    uint32_t arow[4], asw[4], brow[2], bsw[2];
    #pragma unroll
    for (int ma = 0; ma < 4; ma++) {
        int r = wm + ma * 16 + lr;
        arow[ma] = r * 64; asw[ma] = (r >> 1) & 3;
    }
    #pragma unroll
    for (int ng = 0; ng < 2; ng++) {
        int r = wn + ng * 16 + lr;
        brow[ng] = r * 64; bsw[ng] = (r >> 1) & 3;
    }

    issue(0, 0);
    issue(1, 1);
    int stg = 0;
    for (int ch = 0; ch < nch; ch++) {
        if (ch == nch - 1) { CP_WAIT0(); } else { CP_WAIT1(); }
        __syncthreads();
        if (ch + 2 < nch) issue(ch + 2, stg == 0 ? 2 : stg - 1);

        const uint32_t stage = sb + stg * F16_STAGE_B;

        #pragma unroll
        for (int kh = 0; kh < 2; kh++) {
            const uint32_t col = kh * 2 + lc;
            uint32_t af[4][4], bf[2][4];
            #pragma unroll
            for (int ma = 0; ma < 4; ma++)
                LDSM_X4(af[ma], stage + arow[ma] + ((col ^ asw[ma]) << 4));
            #pragma unroll
            for (int ng = 0; ng < 2; ng++)
                LDSM_X4(bf[ng], stage + GBUF_B + brow[ng] + ((col ^ bsw[ng]) << 4));
            #pragma unroll
            for (int ma = 0; ma < 4; ma++)
                #pragma unroll
                for (int na = 0; na < 4; na++) {
                    const int ng = na >> 1, hi = na & 1;
                    mma_f16(acc[ma][na], af[ma], bf[ng][hi], bf[ng][hi + 2]);
                }
        }
        stg = (stg == 2) ? 0 : stg + 1;
    }

    const int gr = lane >> 2, gc = (lane & 3) * 2;
    #pragma unroll
    for (int ma = 0; ma < 4; ma++) {
        #pragma unroll
        for (int na = 0; na < 4; na++) {
            size_t r = (size_t)(m0 + wm + ma * 16 + gr);
            size_t c = (size_t)(n0 + wn + na * 8 + gc);
            *(float2*)&C[r * N + c]       = make_float2(acc[ma][na][0], acc[ma][na][1]);
            *(float2*)&C[(r + 8) * N + c] = make_float2(acc[ma][na][2], acc[ma][na][3]);
        }
    }
}

// ---------------------------------------------------------------------------
// HMMA flash attention: QK split-bf16 (3-term), PV single-fp16 (1-term),
// no-max softmax with 2^-4 guard scale. kv-tile 64, 2-stage K/V pipeline.
// ---------------------------------------------------------------------------
#define BKT  64
#define QSTR 272
#define KSTR 272
#define VSTR 144
#define SM_QB  (128*QSTR)           // 34816 per Q split
#define SM_K   (2*SM_QB)            // 69632
#define KBUF   (BKT*KSTR)           // 17408
#define KSTAGE (2*KBUF)             // 34816
#define SM_V   (SM_K + 2*KSTAGE)    // 139264
#define VBUF   (128*VSTR)           // 18432 (single fp16 split)
#define ATT_SMEM (SM_V + 2*VBUF)    // 176128

__global__ __launch_bounds__(256, 1) void hmma_attn_kernel(
    const __nv_bfloat16* __restrict__ qh_g, const __nv_bfloat16* __restrict__ ql_g,
    const __nv_bfloat16* __restrict__ kh_g, const __nv_bfloat16* __restrict__ kl_g,
    const __half* __restrict__ vt_g, __half* __restrict__ o_g)
{
    extern __shared__ char smem[];
    const uint32_t sb = smem_u32(smem);
    const int qt = blockIdx.x, h = blockIdx.y, b = blockIdx.z;
    const int tid = threadIdx.x, lane = tid & 31, warp = tid >> 5;
    const int lr = lane & 15, lc = lane >> 4;
    const int gr = lane >> 2, gc = (lane & 3) * 2;

    // Q tile cp.async (both splits), folded into group 0
    {
        const char* s0 = (const char*)(qh_g + (size_t)(b * SEQ + qt * 128) * NEMB + h * 128);
        const char* s1 = (const char*)(ql_g + (size_t)(b * SEQ + qt * 128) * NEMB + h * 128);
        #pragma unroll
        for (int i = 0; i < 8; i++) {
            int c = tid + i * 256;
            int row = c >> 4, off = (c & 15) * 16;
            CP_ASYNC16(sb + row * QSTR + off,         s0 + (size_t)row * (NEMB * 2) + off);
            CP_ASYNC16(sb + SM_QB + row * QSTR + off, s1 + (size_t)row * (NEMB * 2) + off);
        }
    }
    auto issue = [&](int kt) {
        uint32_t kb = sb + SM_K + (kt & 1) * KSTAGE;
        uint32_t vb = sb + SM_V + (kt & 1) * VBUF;
        const char* ksh = (const char*)(kh_g + (size_t)(b * SEQ + kt * BKT) * HD);
        const char* ksl = (const char*)(kl_g + (size_t)(b * SEQ + kt * BKT) * HD);
        #pragma unroll
        for (int i = 0; i < 4; i++) {
            int c = tid + i * 256;
            int row = c >> 4, off = (c & 15) * 16;
            CP_ASYNC16(kb + row * KSTR + off,        ksh + (size_t)row * 256 + off);
            CP_ASYNC16(kb + KBUF + row * KSTR + off, ksl + (size_t)row * 256 + off);
        }
        const char* vs = (const char*)(vt_g + (size_t)b * HD * SEQ + kt * BKT);
        #pragma unroll
        for (int i = 0; i < 4; i++) {
            int c = tid + i * 256;
            int row = c >> 3, off = (c & 7) * 16;
            CP_ASYNC16(vb + row * VSTR + off, vs + (size_t)row * (SEQ * 2) + off);
        }
    };
    issue(0); CP_COMMIT();
    issue(1); CP_COMMIT();

    float oacc[16][4] = {};
    float lsum0 = 0.f, lsum1 = 0.f;
    const float SC2 = 0.08838834764831845f * 1.44269504088896f;  // scale * log2(e)

    const uint32_t qah = sb + (warp * 16 + lr) * QSTR + lc * 16;
    const uint32_t qal = qah + SM_QB;

    const int NKT = SEQ / BKT;      // 32
    for (int kt = 0; kt < NKT; kt++) {
        if (kt == NKT - 1) { CP_WAIT0(); } else { CP_WAIT1(); }
        __syncthreads();
        const uint32_t kb = sb + SM_K + (kt & 1) * KSTAGE;
        const uint32_t vb = sb + SM_V + (kt & 1) * VBUF;

        // ---- S = Q @ K^T over 64 keys (split: hh + hl + lh) ----
        float sacc[8][4] = {};
        #pragma unroll
        for (int kh = 0; kh < 8; kh++) {
            uint32_t qfh[4], qfl[4], kfh[4][4], kfl[4][4];
            LDSM_X4(qfh, qah + kh * 32);
            LDSM_X4(qfl, qal + kh * 32);
            #pragma unroll
            for (int g = 0; g < 4; g++) {
                uint32_t ka = kb + (g * 16 + lr) * KSTR + kh * 32 + lc * 16;
                LDSM_X4(kfh[g], ka);
                LDSM_X4(kfl[g], ka + KBUF);
            }
            #pragma unroll
            for (int na = 0; na < 8; na++) {
                const int g = na >> 1, hi = na & 1;
                mma_bf16(sacc[na], qfh, kfh[g][hi], kfh[g][hi + 2]);
                mma_bf16(sacc[na], qfh, kfl[g][hi], kfl[g][hi + 2]);
                mma_bf16(sacc[na], qfl, kfh[g][hi], kfh[g][hi + 2]);
            }
        }

        // ---- P = exp2(S*sc - 4) (guard scale cancels in O/l); fp16 A-frags ----
        uint32_t paf[4][4];
        float l0 = 0.f, l1 = 0.f;
        #pragma unroll
        for (int na = 0; na < 8; na++) {
            float p0 = exp2f(sacc[na][0] * SC2 - 4.0f);
            float p1 = exp2f(sacc[na][1] * SC2 - 4.0f);
            float p2 = exp2f(sacc[na][2] * SC2 - 4.0f);
            float p3 = exp2f(sacc[na][3] * SC2 - 4.0f);
            l0 += p0 + p1; l1 += p2 + p3;
            const int t = na >> 1, half = na & 1;
            paf[t][half * 2 + 0] = pack_f16(p0, p1);
            paf[t][half * 2 + 1] = pack_f16(p2, p3);
        }
        l0 += __shfl_xor_sync(0xffffffffu, l0, 1);
        l0 += __shfl_xor_sync(0xffffffffu, l0, 2);
        l1 += __shfl_xor_sync(0xffffffffu, l1, 1);
        l1 += __shfl_xor_sync(0xffffffffu, l1, 2);
        lsum0 += l0; lsum1 += l1;

        // ---- O += P @ V (single fp16 pass) ----
        #pragma unroll
        for (int nb8 = 0; nb8 < 8; nb8++) {
            uint32_t vf[4][4];
            #pragma unroll
            for (int ka = 0; ka < 4; ka++)
                LDSM_X4(vf[ka], vb + (nb8 * 16 + lr) * VSTR + ka * 32 + lc * 16);
            #pragma unroll
            for (int ns = 0; ns < 2; ns++) {
                const int n = nb8 * 2 + ns;
                #pragma unroll
                for (int t = 0; t < 4; t++)
                    mma_f16(oacc[n], paf[t], vf[t][ns], vf[t][ns + 2]);
            }
        }
        __syncthreads();
        if (kt + 2 < NKT) { issue(kt + 2); CP_COMMIT(); }
    }

    // ---- epilogue: normalize, write fp16 att ----
    const float inv0 = 1.f / lsum0, inv1 = 1.f / lsum1;
    const size_t row0 = (size_t)(b * SEQ + qt * 128 + warp * 16 + gr);
    #pragma unroll
    for (int n = 0; n < 16; n++) {
        const size_t col = (size_t)h * 128 + n * 8 + gc;
        float v0 = oacc[n][0] * inv0, v1 = oacc[n][1] * inv0;
        float v2 = oacc[n][2] * inv1, v3 = oacc[n][3] * inv1;
        *(uint32_t*)&o_g[row0 * NEMB + col]       = pack_f16(v0, v1);
        *(uint32_t*)&o_g[(row0 + 8) * NEMB + col] = pack_f16(v2, v3);
    }
}

// ---------------------------------------------------------------------------
// fp32 -> bf16 hi/lo split
// ---------------------------------------------------------------------------
__global__ void split_kernel(const float* __restrict__ in,
                             __nv_bfloat16* __restrict__ hi,
                             __nv_bfloat16* __restrict__ lo, int n) {
    int i = (blockIdx.x * blockDim.x + threadIdx.x) * 4;
    if (i >= n) return;
    float4 v = *(const float4*)(in + i);
    __nv_bfloat16 h0 = __float2bfloat16(v.x), h1 = __float2bfloat16(v.y);
    __nv_bfloat16 h2 = __float2bfloat16(v.z), h3 = __float2bfloat16(v.w);
    __nv_bfloat162* H = (__nv_bfloat162*)(hi + i);
    __nv_bfloat162* L = (__nv_bfloat162*)(lo + i);
    H[0] = __nv_bfloat162(h0, h1); H[1] = __nv_bfloat162(h2, h3);
    L[0] = __nv_bfloat162(__float2bfloat16(v.x - __bfloat162float(h0)),
                          __float2bfloat16(v.y - __bfloat162float(h1)));
    L[1] = __nv_bfloat162(__float2bfloat16(v.z - __bfloat162float(h2)),
                          __float2bfloat16(v.w - __bfloat162float(h3)));
}

// ---------------------------------------------------------------------------
// transpose + split: w[K][N] fp32 -> hi/lo[N][K] bf16  (for w_attn)
// ---------------------------------------------------------------------------
__global__ void transpose_split_kernel(const float* __restrict__ w,
                                       __nv_bfloat16* __restrict__ hi,
                                       __nv_bfloat16* __restrict__ lo,
                                       int K, int N) {
    __shared__ float t[32][33];
    int n0 = blockIdx.x * 32, k0 = blockIdx.y * 32;
    int tx = threadIdx.x, ty = threadIdx.y;
    #pragma unroll
    for (int r = ty; r < 32; r += 8)
        t[r][tx] = w[(size_t)(k0 + r) * N + n0 + tx];
    __syncthreads();
    #pragma unroll
    for (int r = ty; r < 32; r += 8) {
        float v = t[tx][r];
        __nv_bfloat16 h = __float2bfloat16(v);
        size_t o = (size_t)(n0 + r) * K + k0 + tx;
        hi[o] = h;
        lo[o] = __float2bfloat16(v - __bfloat162float(h));
    }
}

// ---------------------------------------------------------------------------
// transpose to fp16: w[K][N] fp32 -> [N][K] fp16  (for w_out)
// ---------------------------------------------------------------------------
__global__ void transpose_f16_kernel(const float* __restrict__ w,
                                     __half* __restrict__ o16,
                                     int K, int N) {
    __shared__ float t[32][33];
    int n0 = blockIdx.x * 32, k0 = blockIdx.y * 32;
    int tx = threadIdx.x, ty = threadIdx.y;
    #pragma unroll
    for (int r = ty; r < 32; r += 8)
        t[r][tx] = w[(size_t)(k0 + r) * N + n0 + tx];
    __syncthreads();
    #pragma unroll
    for (int r = ty; r < 32; r += 8)
        o16[(size_t)(n0 + r) * K + k0 + tx] = __float2half_rn(t[tx][r]);
}

// ---------------------------------------------------------------------------
// RoPE + split q,k -> bf16 hi/lo
// ---------------------------------------------------------------------------
__global__ void rope_split_kernel(const float* __restrict__ qkv,
                                  __nv_bfloat16* __restrict__ qh, __nv_bfloat16* __restrict__ ql,
                                  __nv_bfloat16* __restrict__ kh, __nv_bfloat16* __restrict__ kl) {
    const int total = ROWS * 17 * 64;
    int idx = blockIdx.x * blockDim.x + threadIdx.x;
    if (idx >= total) return;
    int i    = idx & 63;
    int head = (idx >> 6) % 17;
    int row  = idx / (17 * 64);
    int t    = row & (SEQ - 1);
    int off  = (head < 16) ? head * HD : 2048;
    const float* p = qkv + (size_t)row * QKV_COLS + off;
    float freq = expf(-(4.0f * (float)i + 1.0f) * (9.210340371976184f / 128.0f));
    float ang = (float)t * freq;
    float c = cosf(ang), s = sinf(ang);
    float x1 = p[i], x2 = p[i + 64];
    float y1 = x1 * c - x2 * s;
    float y2 = x2 * c + x1 * s;
    __nv_bfloat16 h1 = __float2bfloat16(y1), h2 = __float2bfloat16(y2);
    if (head < 16) {
        size_t o = (size_t)row * NEMB + head * HD;
        qh[o + i]      = h1;  ql[o + i]      = __float2bfloat16(y1 - __bfloat162float(h1));
        qh[o + i + 64] = h2;  ql[o + i + 64] = __float2bfloat16(y2 - __bfloat162float(h2));
    } else {
        size_t o = (size_t)row * HD;
        kh[o + i]      = h1;  kl[o + i]      = __float2bfloat16(y1 - __bfloat162float(h1));
        kh[o + i + 64] = h2;  kl[o + i + 64] = __float2bfloat16(y2 - __bfloat162float(h2));
    }
}

// ---------------------------------------------------------------------------
// V transpose: qkv[b*SEQ+t][2176+d] -> vt[b][d][t] fp16
// ---------------------------------------------------------------------------
__global__ void vt_f16_kernel(const float* __restrict__ qkv,
                              __half* __restrict__ vt) {
    __shared__ float tile[32][33];
    int t0 = blockIdx.x * 32, d0 = blockIdx.y * 32, b = blockIdx.z;
    int tx = threadIdx.x, ty = threadIdx.y;
    #pragma unroll
    for (int r = ty; r < 32; r += 8)
        tile[r][tx] = qkv[(size_t)(b * SEQ + t0 + r) * QKV_COLS + 2176 + d0 + tx];
    __syncthreads();
    #pragma unroll
    for (int r = ty; r < 32; r += 8)
        vt[((size_t)b * HD + d0 + r) * SEQ + t0 + tx] = __float2half_rn(tile[tx][r]);
}

// ---------------------------------------------------------------------------
extern "C" void kernel_launch(void* const* d_in, const int* in_sizes, int n_in,
                              void* d_out, int out_size) {
    const float* x      = (const float*)d_in[0];
    const float* w_attn = (const float*)d_in[1];
    const float* w_out  = (const float*)d_in[2];
    float* out = (float*)d_out;

    float *qkv;
    __nv_bfloat16 *xhi, *xlo, *wath, *watl, *qhi, *qlo, *khi, *klo;
    __half *woth, *atth, *vth;
    cudaGetSymbolAddress((void**)&qkv,  g_qkv);
    cudaGetSymbolAddress((void**)&xhi,  g_x_hi);
    cudaGetSymbolAddress((void**)&xlo,  g_x_lo);
    cudaGetSymbolAddress((void**)&wath, g_wat_hi);
    cudaGetSymbolAddress((void**)&watl, g_wat_lo);
    cudaGetSymbolAddress((void**)&woth, g_wot_h);
    cudaGetSymbolAddress((void**)&atth, g_att_h);
    cudaGetSymbolAddress((void**)&qhi,  g_q_hi);
    cudaGetSymbolAddress((void**)&qlo,  g_q_lo);
    cudaGetSymbolAddress((void**)&khi,  g_k_hi);
    cudaGetSymbolAddress((void**)&klo,  g_k_lo);
    cudaGetSymbolAddress((void**)&vth,  g_vt_h);

    cudaFuncSetAttribute(hmma_gemm_kernel, cudaFuncAttributeMaxDynamicSharedMemorySize, GEMM_SMEM);
    cudaFuncSetAttribute(hmma_gemm_f16_kernel, cudaFuncAttributeMaxDynamicSharedMemorySize, F16_GEMM_SMEM);
    cudaFuncSetAttribute(hmma_attn_kernel, cudaFuncAttributeMaxDynamicSharedMemorySize, ATT_SMEM);

    // 0) precision splits
    int nx = ROWS * NEMB;
    split_kernel<<<nx / (4 * 256), 256>>>(x, xhi, xlo, nx);
    transpose_split_kernel<<<dim3(QKV_COLS / 32, NEMB / 32), dim3(32, 8)>>>(w_attn, wath, watl, NEMB, QKV_COLS);
    transpose_f16_kernel<<<dim3(NEMB / 32, NEMB / 32), dim3(32, 8)>>>(w_out, woth, NEMB, NEMB);

    // 1) qkv = x @ w_attn  (HMMA split-bf16)
    hmma_gemm_kernel<<<dim3(QKV_COLS / 128, ROWS / 128), 256, GEMM_SMEM>>>(
        xhi, xlo, wath, watl, qkv, ROWS, QKV_COLS, NEMB);

    // 2) RoPE + split q,k ; transpose v -> fp16
    int rope_total = ROWS * 17 * 64;
    rope_split_kernel<<<(rope_total + 255) / 256, 256>>>(qkv, qhi, qlo, khi, klo);
    vt_f16_kernel<<<dim3(SEQ / 32, HD / 32, BATCH), dim3(32, 8)>>>(qkv, vth);

    // 3) HMMA flash attention -> att fp16
    hmma_attn_kernel<<<dim3(SEQ / 128, NHEAD, BATCH), 256, ATT_SMEM>>>(
        qhi, qlo, khi, klo, vth, atth);

    // 4) out = att @ w_out  (HMMA single-fp16)
    hmma_gemm_f16_kernel<<<dim3(NEMB / 128, ROWS / 128), 256, F16_GEMM_SMEM>>>(
        atth, woth, out, ROWS, NEMB, NEMB);
}

// round 17
// speedup vs baseline: 2.6663x; 1.6496x over previous
#include <cuda_runtime.h>
#include <cuda_bf16.h>
#include <cuda_fp16.h>
#include <cstdint>
#include <math.h>

#define BATCH   2
#define SEQ     2048
#define NEMB    2048
#define NHEAD   16
#define HD      128
#define QKV_COLS 2304          // (16+2)*128
#define ROWS    (BATCH*SEQ)    // 4096

// ---------------- scratch (no cudaMalloc allowed) ----------------
__device__ float  g_qkv[ROWS * QKV_COLS];
__device__ __half g_x_h[ROWS * NEMB];
__device__ __half g_wat_h[QKV_COLS * NEMB];   // transposed [N][K]
__device__ __half g_wot_h[NEMB * NEMB];       // transposed [N][K]
__device__ __half g_att_h[ROWS * NEMB];       // attention out
__device__ __half g_q_h[ROWS * NEMB];         // post-RoPE q
__device__ __half g_k_h[ROWS * HD];           // post-RoPE k
__device__ __half g_vt_h[BATCH * HD * SEQ];   // v transposed [b][d][t]

// ---------------- PTX helpers (baseline ISA only: sm_80-class) ----------------
__device__ __forceinline__ uint32_t smem_u32(const void* p) {
    uint32_t a;
    asm("{ .reg .u64 t; cvta.to.shared.u64 t, %1; cvt.u32.u64 %0, t; }" : "=r"(a) : "l"(p));
    return a;
}
#define CP_ASYNC16(s, g) \
    asm volatile("cp.async.cg.shared.global [%0], [%1], 16;" :: "r"(s), "l"(g) : "memory")
#define CP_COMMIT() asm volatile("cp.async.commit_group;" ::: "memory")
#define CP_WAIT1()  asm volatile("cp.async.wait_group 1;" ::: "memory")
#define CP_WAIT0()  asm volatile("cp.async.wait_group 0;" ::: "memory")
#define LDSM_X4(r, a) \
    asm volatile("ldmatrix.sync.aligned.m8n8.x4.shared.b16 {%0,%1,%2,%3}, [%4];" \
        : "=r"((r)[0]), "=r"((r)[1]), "=r"((r)[2]), "=r"((r)[3]) : "r"(a))

__device__ __forceinline__ void mma_f16(float* d, const uint32_t* a, uint32_t b0, uint32_t b1) {
    asm volatile(
        "mma.sync.aligned.m16n8k16.row.col.f32.f16.f16.f32 "
        "{%0,%1,%2,%3}, {%4,%5,%6,%7}, {%8,%9}, {%0,%1,%2,%3};"
        : "+f"(d[0]), "+f"(d[1]), "+f"(d[2]), "+f"(d[3])
        : "r"(a[0]), "r"(a[1]), "r"(a[2]), "r"(a[3]), "r"(b0), "r"(b1));
}
__device__ __forceinline__ uint32_t pack_f16(float x, float y) {
    __half2 t = __floats2half2_rn(x, y);
    return *(uint32_t*)&t;
}

// ---------------------------------------------------------------------------
// HMMA single-fp16 GEMM: C[M,N] fp32 = A[M,K] @ B[N,K]^T, fp32 accumulate.
// 128x128 tile, k-chunk 32, 3-stage cp.async, ONE sync per chunk,
// XOR-swizzled 64B rows; stage = 16KB; 3 stages = 48KB -> 2 CTAs/SM.
// ---------------------------------------------------------------------------
#define GBUF_B   8192
#define F16_STAGE_B (2 * GBUF_B)         // 16384
#define F16_GEMM_SMEM (3 * F16_STAGE_B)  // 49152

__global__ __launch_bounds__(256, 2) void hmma_gemm_f16_kernel(
    const __half* __restrict__ A, const __half* __restrict__ B,
    float* __restrict__ C, int M, int N, int K)
{
    extern __shared__ char smem[];
    const uint32_t sb = smem_u32(smem);
    const int tid  = threadIdx.x;
    const int lane = tid & 31;
    const int warp = tid >> 5;
    const int m0 = blockIdx.y * 128, n0 = blockIdx.x * 128;
    const int wm = (warp >> 2) * 64, wn = (warp & 3) * 32;

    const int crow = tid >> 1;
    const int ccol = (tid & 1) * 2;
    const int csw  = (crow >> 1) & 3;
    const uint32_t cd0 = crow * 64 + ((ccol    ) ^ csw) * 16;
    const uint32_t cd1 = crow * 64 + ((ccol + 1) ^ csw) * 16;
    const char* gsrcA = (const char*)(A + (size_t)(m0 + crow) * K);
    const char* gsrcB = (const char*)(B + (size_t)(n0 + crow) * K);

    const int nch = K / 32;
    float acc[4][4][4] = {};
    const int lr = lane & 15;
    const int lc = lane >> 4;

    auto issue = [&](int ch, int st) {
        const uint32_t so = sb + st * F16_STAGE_B;
        const char* ga = gsrcA + (size_t)ch * 64 + ccol * 16;
        const char* gb = gsrcB + (size_t)ch * 64 + ccol * 16;
        CP_ASYNC16(so + cd0, ga);
        CP_ASYNC16(so + cd1, ga + 16);
        CP_ASYNC16(so + GBUF_B + cd0, gb);
        CP_ASYNC16(so + GBUF_B + cd1, gb + 16);
        CP_COMMIT();
    };

    uint32_t arow[4], asw[4], brow[2], bsw[2];
    #pragma unroll
    for (int ma = 0; ma < 4; ma++) {
        int r = wm + ma * 16 + lr;
        arow[ma] = r * 64; asw[ma] = (r >> 1) & 3;
    }
    #pragma unroll
    for (int ng = 0; ng < 2; ng++) {
        int r = wn + ng * 16 + lr;
        brow[ng] = r * 64; bsw[ng] = (r >> 1) & 3;
    }

    issue(0, 0);
    issue(1, 1);
    int stg = 0;
    for (int ch = 0; ch < nch; ch++) {
        if (ch == nch - 1) { CP_WAIT0(); } else { CP_WAIT1(); }
        __syncthreads();
        if (ch + 2 < nch) issue(ch + 2, stg == 0 ? 2 : stg - 1);

        const uint32_t stage = sb + stg * F16_STAGE_B;

        #pragma unroll
        for (int kh = 0; kh < 2; kh++) {
            const uint32_t col = kh * 2 + lc;
            uint32_t af[4][4], bf[2][4];
            #pragma unroll
            for (int ma = 0; ma < 4; ma++)
                LDSM_X4(af[ma], stage + arow[ma] + ((col ^ asw[ma]) << 4));
            #pragma unroll
            for (int ng = 0; ng < 2; ng++)
                LDSM_X4(bf[ng], stage + GBUF_B + brow[ng] + ((col ^ bsw[ng]) << 4));
            #pragma unroll
            for (int ma = 0; ma < 4; ma++)
                #pragma unroll
                for (int na = 0; na < 4; na++) {
                    const int ng = na >> 1, hi = na & 1;
                    mma_f16(acc[ma][na], af[ma], bf[ng][hi], bf[ng][hi + 2]);
                }
        }
        stg = (stg == 2) ? 0 : stg + 1;
    }

    const int gr = lane >> 2, gc = (lane & 3) * 2;
    #pragma unroll
    for (int ma = 0; ma < 4; ma++) {
        #pragma unroll
        for (int na = 0; na < 4; na++) {
            size_t r = (size_t)(m0 + wm + ma * 16 + gr);
            size_t c = (size_t)(n0 + wn + na * 8 + gc);
            *(float2*)&C[r * N + c]       = make_float2(acc[ma][na][0], acc[ma][na][1]);
            *(float2*)&C[(r + 8) * N + c] = make_float2(acc[ma][na][2], acc[ma][na][3]);
        }
    }
}

// ---------------------------------------------------------------------------
// HMMA flash attention, all-fp16 single-pass (fp32 accum), no-max softmax
// with 2^-4 guard scale. kv-tile 64, 2-stage K/V pipeline.
// Block = (128 q rows, head, batch), 8 warps x (16 q rows x 64 keys).
// ---------------------------------------------------------------------------
#define BKT  64
#define QSTR 272
#define KSTR 272
#define VSTR 144
#define SM_Q   0
#define SM_QSZ (128*QSTR)           // 34816
#define SM_K   SM_QSZ               // 34816
#define KBUF   (BKT*KSTR)           // 17408 per stage
#define SM_V   (SM_K + 2*KBUF)      // 69632
#define VBUF   (128*VSTR)           // 18432 per stage
#define ATT_SMEM (SM_V + 2*VBUF)    // 106496

__global__ __launch_bounds__(256, 1) void hmma_attn_kernel(
    const __half* __restrict__ q_g, const __half* __restrict__ k_g,
    const __half* __restrict__ vt_g, __half* __restrict__ o_g)
{
    extern __shared__ char smem[];
    const uint32_t sb = smem_u32(smem);
    const int qt = blockIdx.x, h = blockIdx.y, b = blockIdx.z;
    const int tid = threadIdx.x, lane = tid & 31, warp = tid >> 5;
    const int lr = lane & 15, lc = lane >> 4;
    const int gr = lane >> 2, gc = (lane & 3) * 2;

    // Q tile cp.async, folded into group 0
    {
        const char* s0 = (const char*)(q_g + (size_t)(b * SEQ + qt * 128) * NEMB + h * 128);
        #pragma unroll
        for (int i = 0; i < 8; i++) {
            int c = tid + i * 256;
            int row = c >> 4, off = (c & 15) * 16;
            CP_ASYNC16(sb + row * QSTR + off, s0 + (size_t)row * (NEMB * 2) + off);
        }
    }
    auto issue = [&](int kt) {
        uint32_t kb = sb + SM_K + (kt & 1) * KBUF;
        uint32_t vb = sb + SM_V + (kt & 1) * VBUF;
        const char* ks = (const char*)(k_g + (size_t)(b * SEQ + kt * BKT) * HD);
        #pragma unroll
        for (int i = 0; i < 4; i++) {
            int c = tid + i * 256;
            int row = c >> 4, off = (c & 15) * 16;
            CP_ASYNC16(kb + row * KSTR + off, ks + (size_t)row * 256 + off);
        }
        const char* vs = (const char*)(vt_g + (size_t)b * HD * SEQ + kt * BKT);
        #pragma unroll
        for (int i = 0; i < 4; i++) {
            int c = tid + i * 256;
            int row = c >> 3, off = (c & 7) * 16;
            CP_ASYNC16(vb + row * VSTR + off, vs + (size_t)row * (SEQ * 2) + off);
        }
    };
    issue(0); CP_COMMIT();
    issue(1); CP_COMMIT();

    float oacc[16][4] = {};
    float lsum0 = 0.f, lsum1 = 0.f;
    const float SC2 = 0.08838834764831845f * 1.44269504088896f;  // scale * log2(e)

    const uint32_t qa = sb + (warp * 16 + lr) * QSTR + lc * 16;

    const int NKT = SEQ / BKT;      // 32
    for (int kt = 0; kt < NKT; kt++) {
        if (kt == NKT - 1) { CP_WAIT0(); } else { CP_WAIT1(); }
        __syncthreads();
        const uint32_t kb = sb + SM_K + (kt & 1) * KBUF;
        const uint32_t vb = sb + SM_V + (kt & 1) * VBUF;

        // ---- S = Q @ K^T over 64 keys (single fp16 pass) ----
        float sacc[8][4] = {};
        #pragma unroll
        for (int kh = 0; kh < 8; kh++) {
            uint32_t qf[4], kf[4][4];
            LDSM_X4(qf, qa + kh * 32);
            #pragma unroll
            for (int g = 0; g < 4; g++)
                LDSM_X4(kf[g], kb + (g * 16 + lr) * KSTR + kh * 32 + lc * 16);
            #pragma unroll
            for (int na = 0; na < 8; na++) {
                const int g = na >> 1, hi = na & 1;
                mma_f16(sacc[na], qf, kf[g][hi], kf[g][hi + 2]);
            }
        }

        // ---- P = exp2(S*sc - 4) (guard scale cancels in O/l); fp16 A-frags ----
        uint32_t paf[4][4];
        float l0 = 0.f, l1 = 0.f;
        #pragma unroll
        for (int na = 0; na < 8; na++) {
            float p0 = exp2f(sacc[na][0] * SC2 - 4.0f);
            float p1 = exp2f(sacc[na][1] * SC2 - 4.0f);
            float p2 = exp2f(sacc[na][2] * SC2 - 4.0f);
            float p3 = exp2f(sacc[na][3] * SC2 - 4.0f);
            l0 += p0 + p1; l1 += p2 + p3;
            const int t = na >> 1, half = na & 1;
            paf[t][half * 2 + 0] = pack_f16(p0, p1);
            paf[t][half * 2 + 1] = pack_f16(p2, p3);
        }
        l0 += __shfl_xor_sync(0xffffffffu, l0, 1);
        l0 += __shfl_xor_sync(0xffffffffu, l0, 2);
        l1 += __shfl_xor_sync(0xffffffffu, l1, 1);
        l1 += __shfl_xor_sync(0xffffffffu, l1, 2);
        lsum0 += l0; lsum1 += l1;

        // ---- O += P @ V (single fp16 pass) ----
        #pragma unroll
        for (int nb8 = 0; nb8 < 8; nb8++) {
            uint32_t vf[4][4];
            #pragma unroll
            for (int ka = 0; ka < 4; ka++)
                LDSM_X4(vf[ka], vb + (nb8 * 16 + lr) * VSTR + ka * 32 + lc * 16);
            #pragma unroll
            for (int ns = 0; ns < 2; ns++) {
                const int n = nb8 * 2 + ns;
                #pragma unroll
                for (int t = 0; t < 4; t++)
                    mma_f16(oacc[n], paf[t], vf[t][ns], vf[t][ns + 2]);
            }
        }
        __syncthreads();
        if (kt + 2 < NKT) { issue(kt + 2); CP_COMMIT(); }
    }

    // ---- epilogue: normalize, write fp16 att ----
    const float inv0 = 1.f / lsum0, inv1 = 1.f / lsum1;
    const size_t row0 = (size_t)(b * SEQ + qt * 128 + warp * 16 + gr);
    #pragma unroll
    for (int n = 0; n < 16; n++) {
        const size_t col = (size_t)h * 128 + n * 8 + gc;
        float v0 = oacc[n][0] * inv0, v1 = oacc[n][1] * inv0;
        float v2 = oacc[n][2] * inv1, v3 = oacc[n][3] * inv1;
        *(uint32_t*)&o_g[row0 * NEMB + col]       = pack_f16(v0, v1);
        *(uint32_t*)&o_g[(row0 + 8) * NEMB + col] = pack_f16(v2, v3);
    }
}

// ---------------------------------------------------------------------------
// fp32 -> fp16 cast
// ---------------------------------------------------------------------------
__global__ void cast_f16_kernel(const float* __restrict__ in,
                                __half* __restrict__ out, int n) {
    int i = (blockIdx.x * blockDim.x + threadIdx.x) * 4;
    if (i >= n) return;
    float4 v = *(const float4*)(in + i);
    __half2* O = (__half2*)(out + i);
    O[0] = __floats2half2_rn(v.x, v.y);
    O[1] = __floats2half2_rn(v.z, v.w);
}

// ---------------------------------------------------------------------------
// transpose to fp16: w[K][N] fp32 -> [N][K] fp16
// ---------------------------------------------------------------------------
__global__ void transpose_f16_kernel(const float* __restrict__ w,
                                     __half* __restrict__ o16,
                                     int K, int N) {
    __shared__ float t[32][33];
    int n0 = blockIdx.x * 32, k0 = blockIdx.y * 32;
    int tx = threadIdx.x, ty = threadIdx.y;
    #pragma unroll
    for (int r = ty; r < 32; r += 8)
        t[r][tx] = w[(size_t)(k0 + r) * N + n0 + tx];
    __syncthreads();
    #pragma unroll
    for (int r = ty; r < 32; r += 8)
        o16[(size_t)(n0 + r) * K + k0 + tx] = __float2half_rn(t[tx][r]);
}

// ---------------------------------------------------------------------------
// RoPE -> fp16 q,k
// ---------------------------------------------------------------------------
__global__ void rope_f16_kernel(const float* __restrict__ qkv,
                                __half* __restrict__ qh, __half* __restrict__ kh) {
    const int total = ROWS * 17 * 64;
    int idx = blockIdx.x * blockDim.x + threadIdx.x;
    if (idx >= total) return;
    int i    = idx & 63;
    int head = (idx >> 6) % 17;
    int row  = idx / (17 * 64);
    int t    = row & (SEQ - 1);
    int off  = (head < 16) ? head * HD : 2048;
    const float* p = qkv + (size_t)row * QKV_COLS + off;
    float freq = expf(-(4.0f * (float)i + 1.0f) * (9.210340371976184f / 128.0f));
    float ang = (float)t * freq;
    float c = cosf(ang), s = sinf(ang);
    float x1 = p[i], x2 = p[i + 64];
    float y1 = x1 * c - x2 * s;
    float y2 = x2 * c + x1 * s;
    if (head < 16) {
        size_t o = (size_t)row * NEMB + head * HD;
        qh[o + i]      = __float2half_rn(y1);
        qh[o + i + 64] = __float2half_rn(y2);
    } else {
        size_t o = (size_t)row * HD;
        kh[o + i]      = __float2half_rn(y1);
        kh[o + i + 64] = __float2half_rn(y2);
    }
}

// ---------------------------------------------------------------------------
// V transpose: qkv[b*SEQ+t][2176+d] -> vt[b][d][t] fp16
// ---------------------------------------------------------------------------
__global__ void vt_f16_kernel(const float* __restrict__ qkv,
                              __half* __restrict__ vt) {
    __shared__ float tile[32][33];
    int t0 = blockIdx.x * 32, d0 = blockIdx.y * 32, b = blockIdx.z;
    int tx = threadIdx.x, ty = threadIdx.y;
    #pragma unroll
    for (int r = ty; r < 32; r += 8)
        tile[r][tx] = qkv[(size_t)(b * SEQ + t0 + r) * QKV_COLS + 2176 + d0 + tx];
    __syncthreads();
    #pragma unroll
    for (int r = ty; r < 32; r += 8)
        vt[((size_t)b * HD + d0 + r) * SEQ + t0 + tx] = __float2half_rn(tile[tx][r]);
}

// ---------------------------------------------------------------------------
extern "C" void kernel_launch(void* const* d_in, const int* in_sizes, int n_in,
                              void* d_out, int out_size) {
    const float* x      = (const float*)d_in[0];
    const float* w_attn = (const float*)d_in[1];
    const float* w_out  = (const float*)d_in[2];
    float* out = (float*)d_out;

    float *qkv;
    __half *xh, *wath, *woth, *atth, *qh, *kh, *vth;
    cudaGetSymbolAddress((void**)&qkv,  g_qkv);
    cudaGetSymbolAddress((void**)&xh,   g_x_h);
    cudaGetSymbolAddress((void**)&wath, g_wat_h);
    cudaGetSymbolAddress((void**)&woth, g_wot_h);
    cudaGetSymbolAddress((void**)&atth, g_att_h);
    cudaGetSymbolAddress((void**)&qh,   g_q_h);
    cudaGetSymbolAddress((void**)&kh,   g_k_h);
    cudaGetSymbolAddress((void**)&vth,  g_vt_h);

    cudaFuncSetAttribute(hmma_gemm_f16_kernel, cudaFuncAttributeMaxDynamicSharedMemorySize, F16_GEMM_SMEM);
    cudaFuncSetAttribute(hmma_attn_kernel, cudaFuncAttributeMaxDynamicSharedMemorySize, ATT_SMEM);

    // 0) fp16 conversions
    int nx = ROWS * NEMB;
    cast_f16_kernel<<<nx / (4 * 256), 256>>>(x, xh, nx);
    transpose_f16_kernel<<<dim3(QKV_COLS / 32, NEMB / 32), dim3(32, 8)>>>(w_attn, wath, NEMB, QKV_COLS);
    transpose_f16_kernel<<<dim3(NEMB / 32, NEMB / 32), dim3(32, 8)>>>(w_out, woth, NEMB, NEMB);

    // 1) qkv = x @ w_attn  (HMMA fp16 single-pass)
    hmma_gemm_f16_kernel<<<dim3(QKV_COLS / 128, ROWS / 128), 256, F16_GEMM_SMEM>>>(
        xh, wath, qkv, ROWS, QKV_COLS, NEMB);

    // 2) RoPE -> fp16 q,k ; transpose v -> fp16
    int rope_total = ROWS * 17 * 64;
    rope_f16_kernel<<<(rope_total + 255) / 256, 256>>>(qkv, qh, kh);
    vt_f16_kernel<<<dim3(SEQ / 32, HD / 32, BATCH), dim3(32, 8)>>>(qkv, vth);

    // 3) HMMA flash attention (all fp16) -> att fp16
    hmma_attn_kernel<<<dim3(SEQ / 128, NHEAD, BATCH), 256, ATT_SMEM>>>(
        qh, kh, vth, atth);

    // 4) out = att @ w_out  (HMMA fp16 single-pass)
    hmma_gemm_f16_kernel<<<dim3(NEMB / 128, ROWS / 128), 256, F16_GEMM_SMEM>>>(
        atth, woth, out, ROWS, NEMB, NEMB);
}